// round 2
// baseline (speedup 1.0000x reference)
#include <cuda_runtime.h>
#include <cuda_bf16.h>
#include <cstdint>

#define Hd 1024
#define Vv 32000
#define Bb 64
#define Ss 64
#define Tt 13
#define SOS_TOK 2

// ---------------- static scratch (no allocations allowed) ----------------
__device__ float g_keys[Bb * Ss * Hd];     // keys_proj [B*S, H]
__device__ float g_h[Bb * Hd];             // hidden state
__device__ float g_c[Bb * Hd];             // cell state
__device__ float g_q[Bb * Hd];             // attention query
__device__ float g_xi[Bb * 2 * Hd];        // [x | ctx]
__device__ float g_gates[Bb * 4 * Hd];     // LSTM gates
__device__ float g_nh[Tt * Bb * Hd];       // all LayerNorm outputs, row = t*B + b

// ---------------- bf16 tensor-core GEMM: C[M,N] = A[M,K] @ B[N,K]^T ------
// A, B are fp32 in gmem, converted to bf16 on the smem-load path.
// SPLIT=1: split-bf16 (hi+lo) operands, 3 MMAs per product -> ~fp32 accuracy.
// Optional second (A2,B2,K2) pair accumulated into the same tile (for
// gates = xi@W_ih^T + h@W_hh^T). Optional bias1/bias2. Optional row remap
// for the logits GEMM: out_row = (m % 64)*13 + (m / 64)  (maps t*B+b -> b*T+t).
__device__ __forceinline__ void mma16816(float* d, const uint32_t* a, const uint32_t* b) {
    asm volatile(
        "mma.sync.aligned.m16n8k16.row.col.f32.bf16.bf16.f32 "
        "{%0,%1,%2,%3}, {%4,%5,%6,%7}, {%8,%9}, {%0,%1,%2,%3};\n"
        : "+f"(d[0]), "+f"(d[1]), "+f"(d[2]), "+f"(d[3])
        : "r"(a[0]), "r"(a[1]), "r"(a[2]), "r"(a[3]), "r"(b[0]), "r"(b[1]));
}

template<int SPLIT>
__global__ void __launch_bounds__(128)
gemm_bf16(const float* __restrict__ A1, const float* __restrict__ B1, int K1,
          const float* __restrict__ A2, const float* __restrict__ B2, int K2,
          float* __restrict__ C, int N,
          const float* __restrict__ bias1, const float* __restrict__ bias2,
          int remap)
{
    // [0] = hi plane, [1] = lo plane (lo only used when SPLIT)
    __shared__ __nv_bfloat16 As[SPLIT ? 2 : 1][64][40];  // +8 pad
    __shared__ __nv_bfloat16 Bs[SPLIT ? 2 : 1][64][40];

    const int tid  = threadIdx.x;
    const int wid  = tid >> 5, lane = tid & 31;
    const int wm   = wid & 1,  wn   = wid >> 1;     // 2x2 warp grid, 32x32 per warp
    const int g    = lane >> 2, tg  = lane & 3;
    const int m0   = blockIdx.y * 64;
    const int n0   = blockIdx.x * 64;
    const int lr   = tid >> 3;                       // gmem load row (0..15)
    const int lc   = (tid & 7) << 2;                 // gmem load col (float4)

    float acc[2][4][4];
#pragma unroll
    for (int i = 0; i < 2; i++)
#pragma unroll
        for (int j = 0; j < 4; j++)
#pragma unroll
            for (int k = 0; k < 4; k++) acc[i][j][k] = 0.f;

#pragma unroll 1
    for (int part = 0; part < 2; ++part) {
        const float* A  = part ? A2 : A1;
        const float* Bw = part ? B2 : B1;
        const int    K  = part ? K2 : K1;
        if (A == nullptr) break;

#pragma unroll 1
        for (int k0 = 0; k0 < K; k0 += 32) {
            // load + convert 64x32 fp32 tiles of A and B into bf16 smem
#pragma unroll
            for (int i = 0; i < 4; ++i) {
                int row = lr + i * 16;
                float4 va = *(const float4*)(A + (size_t)(m0 + row) * K + (k0 + lc));
                float4 vb = *(const float4*)(Bw + (size_t)(n0 + row) * K + (k0 + lc));
                float av[4] = {va.x, va.y, va.z, va.w};
                float bv[4] = {vb.x, vb.y, vb.z, vb.w};
#pragma unroll
                for (int e = 0; e < 4; ++e) {
                    __nv_bfloat16 ah = __float2bfloat16(av[e]);
                    __nv_bfloat16 bh = __float2bfloat16(bv[e]);
                    As[0][row][lc + e] = ah;
                    Bs[0][row][lc + e] = bh;
                    if (SPLIT) {
                        As[1][row][lc + e] = __float2bfloat16(av[e] - __bfloat162float(ah));
                        Bs[1][row][lc + e] = __float2bfloat16(bv[e] - __bfloat162float(bh));
                    }
                }
            }
            __syncthreads();

#pragma unroll
            for (int ki = 0; ki < 2; ++ki) {
                const int kb = ki * 16;
                uint32_t af[2][4], al[2][4];
                uint32_t bf[4][2], bl[4][2];
#pragma unroll
                for (int mi = 0; mi < 2; mi++) {
                    int r = wm * 32 + mi * 16 + g;
                    af[mi][0] = *(const uint32_t*)&As[0][r][kb + 2 * tg];
                    af[mi][1] = *(const uint32_t*)&As[0][r + 8][kb + 2 * tg];
                    af[mi][2] = *(const uint32_t*)&As[0][r][kb + 2 * tg + 8];
                    af[mi][3] = *(const uint32_t*)&As[0][r + 8][kb + 2 * tg + 8];
                    if (SPLIT) {
                        al[mi][0] = *(const uint32_t*)&As[1][r][kb + 2 * tg];
                        al[mi][1] = *(const uint32_t*)&As[1][r + 8][kb + 2 * tg];
                        al[mi][2] = *(const uint32_t*)&As[1][r][kb + 2 * tg + 8];
                        al[mi][3] = *(const uint32_t*)&As[1][r + 8][kb + 2 * tg + 8];
                    }
                }
#pragma unroll
                for (int ni = 0; ni < 4; ni++) {
                    int r = wn * 32 + ni * 8 + g;
                    bf[ni][0] = *(const uint32_t*)&Bs[0][r][kb + 2 * tg];
                    bf[ni][1] = *(const uint32_t*)&Bs[0][r][kb + 2 * tg + 8];
                    if (SPLIT) {
                        bl[ni][0] = *(const uint32_t*)&Bs[1][r][kb + 2 * tg];
                        bl[ni][1] = *(const uint32_t*)&Bs[1][r][kb + 2 * tg + 8];
                    }
                }
#pragma unroll
                for (int mi = 0; mi < 2; mi++)
#pragma unroll
                    for (int ni = 0; ni < 4; ni++) {
                        mma16816(acc[mi][ni], af[mi], bf[ni]);
                        if (SPLIT) {
                            mma16816(acc[mi][ni], af[mi], bl[ni]);   // ahi*blo
                            mma16816(acc[mi][ni], al[mi], bf[ni]);   // alo*bhi
                        }
                    }
            }
            __syncthreads();
        }
    }

    // epilogue: bias add + optional row remap + store
#pragma unroll
    for (int mi = 0; mi < 2; mi++) {
#pragma unroll
        for (int half = 0; half < 2; ++half) {
            int row = m0 + wm * 32 + mi * 16 + g + half * 8;
            size_t orow = remap ? (size_t)((row & 63) * Tt + (row >> 6)) : (size_t)row;
#pragma unroll
            for (int ni = 0; ni < 4; ni++) {
                int col = n0 + wn * 32 + ni * 8 + 2 * tg;
                float b0 = bias1 ? bias1[col]     : 0.f;
                float b1 = bias1 ? bias1[col + 1] : 0.f;
                if (bias2) { b0 += bias2[col]; b1 += bias2[col + 1]; }
                float2 v;
                v.x = acc[mi][ni][half * 2 + 0] + b0;
                v.y = acc[mi][ni][half * 2 + 1] + b1;
                *(float2*)(C + orow * (size_t)N + col) = v;
            }
        }
    }
}

// ---------------- per-step fused attention kernel ------------------------
__global__ void __launch_bounds__(256)
attend(const float* __restrict__ enc, const float* __restrict__ Va,
       const float* __restrict__ bv, const float* __restrict__ emb,
       const int* __restrict__ target, float* __restrict__ out_attn, int t)
{
    const int b = blockIdx.x, tid = threadIdx.x;
    __shared__ float qs[Hd];
    __shared__ float sc[Ss];

    for (int k = tid; k < Hd; k += 256) qs[k] = g_q[b * Hd + k];
    __syncthreads();

    const int wid = tid >> 5, lane = tid & 31;
    for (int s = wid; s < Ss; s += 8) {
        const float* kr = g_keys + ((size_t)(b * Ss + s)) * Hd;
        float acc = 0.f;
        for (int k = lane; k < Hd; k += 32)
            acc += tanhf(qs[k] + kr[k]) * Va[k];
#pragma unroll
        for (int o = 16; o; o >>= 1) acc += __shfl_xor_sync(0xffffffffu, acc, o);
        if (lane == 0) sc[s] = acc + bv[0];
    }
    __syncthreads();

    if (wid == 0) {  // softmax over 64 scores, warp 0
        float v0 = sc[lane], v1 = sc[lane + 32];
        float m = fmaxf(v0, v1);
#pragma unroll
        for (int o = 16; o; o >>= 1) m = fmaxf(m, __shfl_xor_sync(0xffffffffu, m, o));
        float e0 = __expf(v0 - m), e1 = __expf(v1 - m);
        float s = e0 + e1;
#pragma unroll
        for (int o = 16; o; o >>= 1) s += __shfl_xor_sync(0xffffffffu, s, o);
        float inv = 1.f / s;
        sc[lane] = e0 * inv; sc[lane + 32] = e1 * inv;
    }
    __syncthreads();

    if (tid < Ss) out_attn[((size_t)b * Tt + t) * Ss + tid] = sc[tid];

    int tok = (t == 0) ? SOS_TOK : target[b * Tt + (t - 1)];
    for (int h = tid; h < Hd; h += 256) {
        float acc = 0.f;
#pragma unroll 8
        for (int s = 0; s < Ss; s++)
            acc += sc[s] * enc[((size_t)(b * Ss + s)) * Hd + h];
        g_xi[b * 2 * Hd + Hd + h] = acc;               // ctx half
        g_xi[b * 2 * Hd + h] = emb[(size_t)tok * Hd + h];  // x half
    }
}

// ---------------- LSTM cell + LayerNorm ----------------------------------
__device__ __forceinline__ float sigmoidf_(float x) { return 1.f / (1.f + expf(-x)); }

__global__ void __launch_bounds__(256)
cell(const float* __restrict__ ln_g, const float* __restrict__ ln_b, int t)
{
    const int b = blockIdx.x, tid = threadIdx.x;
    const int wid = tid >> 5, lane = tid & 31;
    __shared__ float r1[8], r2[8];

    float hv[4];
    float s1 = 0.f, s2 = 0.f;
#pragma unroll
    for (int i = 0; i < 4; i++) {
        int j = tid + i * 256;
        float gi = g_gates[b * 4 * Hd + j];
        float gf = g_gates[b * 4 * Hd + Hd + j];
        float gg = g_gates[b * 4 * Hd + 2 * Hd + j];
        float go = g_gates[b * 4 * Hd + 3 * Hd + j];
        float cv = sigmoidf_(gf) * g_c[b * Hd + j] + sigmoidf_(gi) * tanhf(gg);
        g_c[b * Hd + j] = cv;
        float hh = sigmoidf_(go) * tanhf(cv);
        g_h[b * Hd + j] = hh;
        hv[i] = hh; s1 += hh; s2 += hh * hh;
    }
#pragma unroll
    for (int o = 16; o; o >>= 1) {
        s1 += __shfl_xor_sync(0xffffffffu, s1, o);
        s2 += __shfl_xor_sync(0xffffffffu, s2, o);
    }
    if (lane == 0) { r1[wid] = s1; r2[wid] = s2; }
    __syncthreads();
    if (wid == 0) {
        float a = (lane < 8) ? r1[lane] : 0.f;
        float q = (lane < 8) ? r2[lane] : 0.f;
#pragma unroll
        for (int o = 4; o; o >>= 1) {
            a += __shfl_xor_sync(0xffffffffu, a, o);
            q += __shfl_xor_sync(0xffffffffu, q, o);
        }
        if (lane == 0) { r1[0] = a; r2[0] = q; }
    }
    __syncthreads();
    float mu  = r1[0] * (1.f / Hd);
    float var = r2[0] * (1.f / Hd) - mu * mu;
    float inv = rsqrtf(var + 1e-5f);
#pragma unroll
    for (int i = 0; i < 4; i++) {
        int j = tid + i * 256;
        g_nh[((size_t)t * Bb + b) * Hd + j] = (hv[i] - mu) * inv * ln_g[j] + ln_b[j];
    }
}

// ---------------- log-softmax in place over V ----------------------------
__global__ void __launch_bounds__(256)
logsoftmax(float* __restrict__ out)
{
    const size_t base = (size_t)blockIdx.x * Vv;
    const int tid = threadIdx.x;
    const int wid = tid >> 5, lane = tid & 31;
    __shared__ float red[9];

    float m = -1e30f;
    for (int i = tid; i < Vv; i += 256) m = fmaxf(m, out[base + i]);
#pragma unroll
    for (int o = 16; o; o >>= 1) m = fmaxf(m, __shfl_xor_sync(0xffffffffu, m, o));
    if (lane == 0) red[wid] = m;
    __syncthreads();
    if (wid == 0) {
        float mm = (lane < 8) ? red[lane] : -1e30f;
#pragma unroll
        for (int o = 4; o; o >>= 1) mm = fmaxf(mm, __shfl_xor_sync(0xffffffffu, mm, o));
        if (lane == 0) red[8] = mm;
    }
    __syncthreads();
    m = red[8];
    __syncthreads();  // protect red reuse

    float s = 0.f;
    for (int i = tid; i < Vv; i += 256) s += __expf(out[base + i] - m);
#pragma unroll
    for (int o = 16; o; o >>= 1) s += __shfl_xor_sync(0xffffffffu, s, o);
    if (lane == 0) red[wid] = s;
    __syncthreads();
    if (wid == 0) {
        float ss = (lane < 8) ? red[lane] : 0.f;
#pragma unroll
        for (int o = 4; o; o >>= 1) ss += __shfl_xor_sync(0xffffffffu, ss, o);
        if (lane == 0) red[8] = ss;
    }
    __syncthreads();
    float lse = m + logf(red[8]);
    for (int i = tid; i < Vv; i += 256) out[base + i] -= lse;
}

// ---------------- state init / final copies ------------------------------
__global__ void init_state(const float* __restrict__ h0, const float* __restrict__ c0)
{
    int i = blockIdx.x * blockDim.x + threadIdx.x;
    if (i < Bb * Hd) { g_h[i] = h0[i]; g_c[i] = c0[i]; }
}

__global__ void copy_hc(float* __restrict__ out)
{
    int i = blockIdx.x * blockDim.x + threadIdx.x;
    if (i < Bb * Hd) {
        out[(size_t)Bb * Tt * Vv + i] = g_h[i];
        out[(size_t)Bb * Tt * Vv + (size_t)Bb * Hd + i] = g_c[i];
    }
}

// ---------------- launch ---------------------------------------------------
extern "C" void kernel_launch(void* const* d_in, const int* in_sizes, int n_in,
                              void* d_out, int out_size)
{
    (void)in_sizes; (void)n_in; (void)out_size;
    const float* enc    = (const float*)d_in[0];
    const float* enc_h  = (const float*)d_in[1];
    const float* enc_c  = (const float*)d_in[2];
    const int*   target = (const int*)  d_in[3];
    const float* emb    = (const float*)d_in[4];
    const float* Wa     = (const float*)d_in[5];
    const float* ba     = (const float*)d_in[6];
    const float* Ua     = (const float*)d_in[7];
    const float* bu     = (const float*)d_in[8];
    const float* Va     = (const float*)d_in[9];
    const float* bv     = (const float*)d_in[10];
    const float* W_ih   = (const float*)d_in[11];
    const float* W_hh   = (const float*)d_in[12];
    const float* b_ih   = (const float*)d_in[13];
    const float* b_hh   = (const float*)d_in[14];
    const float* ln_g   = (const float*)d_in[15];
    const float* ln_b   = (const float*)d_in[16];
    const float* outW   = (const float*)d_in[17];
    const float* outb   = (const float*)d_in[18];
    float* out = (float*)d_out;

    float *keys, *h, *q, *xi, *gates, *nh;
    cudaGetSymbolAddress((void**)&keys,  g_keys);
    cudaGetSymbolAddress((void**)&h,     g_h);
    cudaGetSymbolAddress((void**)&q,     g_q);
    cudaGetSymbolAddress((void**)&xi,    g_xi);
    cudaGetSymbolAddress((void**)&gates, g_gates);
    cudaGetSymbolAddress((void**)&nh,    g_nh);

    float* out_attn = out + (size_t)Bb * Tt * Vv + 2 * (size_t)Bb * Hd;

    init_state<<<(Bb * Hd + 511) / 512, 512>>>(enc_h, enc_c);

    // keys_proj = enc @ Ua^T + bu   [4096,1024]  (split precision: feeds tanh)
    gemm_bf16<1><<<dim3(Hd / 64, (Bb * Ss) / 64), 128>>>(
        enc, Ua, Hd, nullptr, nullptr, 0, keys, Hd, bu, nullptr, 0);

    for (int t = 0; t < Tt; t++) {
        // q = h @ Wa^T + ba   [64,1024]  (split)
        gemm_bf16<1><<<dim3(Hd / 64, 1), 128>>>(
            h, Wa, Hd, nullptr, nullptr, 0, q, Hd, ba, nullptr, 0);
        // attention + softmax + attn write + ctx + embedding gather
        attend<<<Bb, 256>>>(enc, Va, bv, emb, target, out_attn, t);
        // gates = xi @ W_ih^T + h @ W_hh^T + b_ih + b_hh   [64,4096]  (split)
        gemm_bf16<1><<<dim3((4 * Hd) / 64, 1), 128>>>(
            xi, W_ih, 2 * Hd, h, W_hh, Hd, gates, 4 * Hd, b_ih, b_hh, 0);
        // LSTM cell + LayerNorm -> g_nh[t]
        cell<<<Bb, 256>>>(ln_g, ln_b, t);
    }

    // batched output projection with row remap (t*B+b -> b*T+t), plain bf16
    gemm_bf16<0><<<dim3(Vv / 64, (Tt * Bb) / 64), 128>>>(
        nh, outW, Hd, nullptr, nullptr, 0, out, Vv, outb, nullptr, 1);

    // in-place log-softmax over V for each of the 832 rows
    logsoftmax<<<Tt * Bb, 256>>>(out);

    // final h, c
    copy_hc<<<(Bb * Hd + 511) / 512, 512>>>(out);
}

// round 3
// speedup vs baseline: 2.7455x; 2.7455x over previous
#include <cuda_runtime.h>
#include <cuda_bf16.h>
#include <cstdint>

#define Hd 1024
#define Vv 32000
#define Bb 64
#define Ss 64
#define Tt 13
#define SOS_TOK 2

// ---------------- static scratch (no allocations allowed) ----------------
__device__ float g_keys[Bb * Ss * Hd];        // keys_proj [B*S, H]
__device__ float g_h[Bb * Hd];                // hidden state
__device__ float g_c[Bb * Hd];                // cell state
__device__ float g_qp[4][Bb * Hd];            // q split-K partials
__device__ float g_gp[6][Bb * 4 * Hd];        // gates split-K partials
__device__ float g_sc[Bb * Ss];               // raw attention scores
__device__ float g_xi[Bb * 2 * Hd];           // [x | ctx]
__device__ __nv_bfloat16 g_nhb[896 * Hd];     // LN outputs (bf16), row=t*B+b, padded to 896
__device__ __nv_bfloat16 g_outWb[(size_t)Vv * Hd];  // outW converted to bf16

// ---------------- mma helper ---------------------------------------------
__device__ __forceinline__ void mma16816(float* d, const uint32_t* a, const uint32_t* b) {
    asm volatile(
        "mma.sync.aligned.m16n8k16.row.col.f32.bf16.bf16.f32 "
        "{%0,%1,%2,%3}, {%4,%5,%6,%7}, {%8,%9}, {%0,%1,%2,%3};\n"
        : "+f"(d[0]), "+f"(d[1]), "+f"(d[2]), "+f"(d[3])
        : "r"(a[0]), "r"(a[1]), "r"(a[2]), "r"(a[3]), "r"(b[0]), "r"(b[1]));
}

// ================= split-K split-bf16 GEMM for recurrence =================
// Computes partial C_slice = A[64, kslice] @ B[N, kslice]^T  (fp32 in, split-bf16 mma)
// blockIdx.x = n-tile (64 wide), blockIdx.y = slice.
// slice < ns1 -> (A1,B1,K1), else -> (A2,B2,K2). Slice width = kw.
// Partials at Cp + slice*64*N.
__global__ void __launch_bounds__(128)
splitk_gemm(const float* __restrict__ A1, const float* __restrict__ B1, int K1, int ns1,
            const float* __restrict__ A2, const float* __restrict__ B2, int K2,
            int kw, int N, float* __restrict__ Cp)
{
    __shared__ __nv_bfloat16 As[2][64][40];   // [hi/lo][row][k] (+8 pad)
    __shared__ __nv_bfloat16 Bs[2][64][40];

    const int s   = blockIdx.y;
    const float* A;  const float* Bw;  int K, kb0;
    if (s < ns1) { A = A1; Bw = B1; K = K1; kb0 = s * kw; }
    else         { A = A2; Bw = B2; K = K2; kb0 = (s - ns1) * kw; }

    const int tid  = threadIdx.x;
    const int wid  = tid >> 5, lane = tid & 31;
    const int wm   = wid & 1,  wn   = wid >> 1;
    const int g    = lane >> 2, tg  = lane & 3;
    const int n0   = blockIdx.x * 64;
    const int lr   = tid >> 3;
    const int lc   = (tid & 7) << 2;

    float acc[2][4][4];
#pragma unroll
    for (int i = 0; i < 2; i++)
#pragma unroll
        for (int j = 0; j < 4; j++)
#pragma unroll
            for (int k = 0; k < 4; k++) acc[i][j][k] = 0.f;

#pragma unroll 1
    for (int k0 = kb0; k0 < kb0 + kw; k0 += 32) {
#pragma unroll
        for (int i = 0; i < 4; ++i) {
            int row = lr + i * 16;
            float4 va = *(const float4*)(A + (size_t)row * K + (k0 + lc));
            float4 vb = *(const float4*)(Bw + (size_t)(n0 + row) * K + (k0 + lc));
            float av[4] = {va.x, va.y, va.z, va.w};
            float bv[4] = {vb.x, vb.y, vb.z, vb.w};
#pragma unroll
            for (int e = 0; e < 4; ++e) {
                __nv_bfloat16 ah = __float2bfloat16(av[e]);
                __nv_bfloat16 bh = __float2bfloat16(bv[e]);
                As[0][row][lc + e] = ah;
                Bs[0][row][lc + e] = bh;
                As[1][row][lc + e] = __float2bfloat16(av[e] - __bfloat162float(ah));
                Bs[1][row][lc + e] = __float2bfloat16(bv[e] - __bfloat162float(bh));
            }
        }
        __syncthreads();

#pragma unroll
        for (int ki = 0; ki < 2; ++ki) {
            const int kb = ki * 16;
            uint32_t af[2][4], al[2][4], bf[4][2], bl[4][2];
#pragma unroll
            for (int mi = 0; mi < 2; mi++) {
                int r = wm * 32 + mi * 16 + g;
                af[mi][0] = *(const uint32_t*)&As[0][r][kb + 2 * tg];
                af[mi][1] = *(const uint32_t*)&As[0][r + 8][kb + 2 * tg];
                af[mi][2] = *(const uint32_t*)&As[0][r][kb + 2 * tg + 8];
                af[mi][3] = *(const uint32_t*)&As[0][r + 8][kb + 2 * tg + 8];
                al[mi][0] = *(const uint32_t*)&As[1][r][kb + 2 * tg];
                al[mi][1] = *(const uint32_t*)&As[1][r + 8][kb + 2 * tg];
                al[mi][2] = *(const uint32_t*)&As[1][r][kb + 2 * tg + 8];
                al[mi][3] = *(const uint32_t*)&As[1][r + 8][kb + 2 * tg + 8];
            }
#pragma unroll
            for (int ni = 0; ni < 4; ni++) {
                int r = wn * 32 + ni * 8 + g;
                bf[ni][0] = *(const uint32_t*)&Bs[0][r][kb + 2 * tg];
                bf[ni][1] = *(const uint32_t*)&Bs[0][r][kb + 2 * tg + 8];
                bl[ni][0] = *(const uint32_t*)&Bs[1][r][kb + 2 * tg];
                bl[ni][1] = *(const uint32_t*)&Bs[1][r][kb + 2 * tg + 8];
            }
#pragma unroll
            for (int mi = 0; mi < 2; mi++)
#pragma unroll
                for (int ni = 0; ni < 4; ni++) {
                    mma16816(acc[mi][ni], af[mi], bf[ni]);
                    mma16816(acc[mi][ni], af[mi], bl[ni]);
                    mma16816(acc[mi][ni], al[mi], bf[ni]);
                }
        }
        __syncthreads();
    }

    float* out = Cp + (size_t)s * 64 * N;
#pragma unroll
    for (int mi = 0; mi < 2; mi++)
#pragma unroll
        for (int half = 0; half < 2; ++half) {
            int row = wm * 32 + mi * 16 + g + half * 8;
#pragma unroll
            for (int ni = 0; ni < 4; ni++) {
                int col = n0 + wn * 32 + ni * 8 + 2 * tg;
                float2 v;
                v.x = acc[mi][ni][half * 2 + 0];
                v.y = acc[mi][ni][half * 2 + 1];
                *(float2*)(out + (size_t)row * N + col) = v;
            }
        }
}

// ================= keys GEMM (once): enc @ Ua^T + bu, split-bf16 ==========
__global__ void __launch_bounds__(128)
keys_gemm(const float* __restrict__ A1, const float* __restrict__ B1,
          float* __restrict__ C, const float* __restrict__ bias1)
{
    const int K1 = Hd, N = Hd;
    __shared__ __nv_bfloat16 As[2][64][40];
    __shared__ __nv_bfloat16 Bs[2][64][40];

    const int tid  = threadIdx.x;
    const int wid  = tid >> 5, lane = tid & 31;
    const int wm   = wid & 1,  wn   = wid >> 1;
    const int g    = lane >> 2, tg  = lane & 3;
    const int m0   = blockIdx.y * 64;
    const int n0   = blockIdx.x * 64;
    const int lr   = tid >> 3;
    const int lc   = (tid & 7) << 2;

    float acc[2][4][4];
#pragma unroll
    for (int i = 0; i < 2; i++)
#pragma unroll
        for (int j = 0; j < 4; j++)
#pragma unroll
            for (int k = 0; k < 4; k++) acc[i][j][k] = 0.f;

#pragma unroll 1
    for (int k0 = 0; k0 < K1; k0 += 32) {
#pragma unroll
        for (int i = 0; i < 4; ++i) {
            int row = lr + i * 16;
            float4 va = *(const float4*)(A1 + (size_t)(m0 + row) * K1 + (k0 + lc));
            float4 vb = *(const float4*)(B1 + (size_t)(n0 + row) * K1 + (k0 + lc));
            float av[4] = {va.x, va.y, va.z, va.w};
            float bv[4] = {vb.x, vb.y, vb.z, vb.w};
#pragma unroll
            for (int e = 0; e < 4; ++e) {
                __nv_bfloat16 ah = __float2bfloat16(av[e]);
                __nv_bfloat16 bh = __float2bfloat16(bv[e]);
                As[0][row][lc + e] = ah;
                Bs[0][row][lc + e] = bh;
                As[1][row][lc + e] = __float2bfloat16(av[e] - __bfloat162float(ah));
                Bs[1][row][lc + e] = __float2bfloat16(bv[e] - __bfloat162float(bh));
            }
        }
        __syncthreads();

#pragma unroll
        for (int ki = 0; ki < 2; ++ki) {
            const int kb = ki * 16;
            uint32_t af[2][4], al[2][4], bf[4][2], bl[4][2];
#pragma unroll
            for (int mi = 0; mi < 2; mi++) {
                int r = wm * 32 + mi * 16 + g;
                af[mi][0] = *(const uint32_t*)&As[0][r][kb + 2 * tg];
                af[mi][1] = *(const uint32_t*)&As[0][r + 8][kb + 2 * tg];
                af[mi][2] = *(const uint32_t*)&As[0][r][kb + 2 * tg + 8];
                af[mi][3] = *(const uint32_t*)&As[0][r + 8][kb + 2 * tg + 8];
                al[mi][0] = *(const uint32_t*)&As[1][r][kb + 2 * tg];
                al[mi][1] = *(const uint32_t*)&As[1][r + 8][kb + 2 * tg];
                al[mi][2] = *(const uint32_t*)&As[1][r][kb + 2 * tg + 8];
                al[mi][3] = *(const uint32_t*)&As[1][r + 8][kb + 2 * tg + 8];
            }
#pragma unroll
            for (int ni = 0; ni < 4; ni++) {
                int r = wn * 32 + ni * 8 + g;
                bf[ni][0] = *(const uint32_t*)&Bs[0][r][kb + 2 * tg];
                bf[ni][1] = *(const uint32_t*)&Bs[0][r][kb + 2 * tg + 8];
                bl[ni][0] = *(const uint32_t*)&Bs[1][r][kb + 2 * tg];
                bl[ni][1] = *(const uint32_t*)&Bs[1][r][kb + 2 * tg + 8];
            }
#pragma unroll
            for (int mi = 0; mi < 2; mi++)
#pragma unroll
                for (int ni = 0; ni < 4; ni++) {
                    mma16816(acc[mi][ni], af[mi], bf[ni]);
                    mma16816(acc[mi][ni], af[mi], bl[ni]);
                    mma16816(acc[mi][ni], al[mi], bf[ni]);
                }
        }
        __syncthreads();
    }

#pragma unroll
    for (int mi = 0; mi < 2; mi++)
#pragma unroll
        for (int half = 0; half < 2; ++half) {
            int row = m0 + wm * 32 + mi * 16 + g + half * 8;
#pragma unroll
            for (int ni = 0; ni < 4; ni++) {
                int col = n0 + wn * 32 + ni * 8 + 2 * tg;
                float2 v;
                v.x = acc[mi][ni][half * 2 + 0] + bias1[col];
                v.y = acc[mi][ni][half * 2 + 1] + bias1[col + 1];
                *(float2*)(C + (size_t)row * N + col) = v;
            }
        }
}

// ================= scores: one block per (b, s) ==========================
__global__ void __launch_bounds__(128)
scores_k(const float* __restrict__ Va, const float* __restrict__ ba,
         const float* __restrict__ bv)
{
    const int b = blockIdx.x, s = blockIdx.y;
    const int tid = threadIdx.x;
    const float* kr = g_keys + ((size_t)(b * Ss + s)) * Hd;

    float acc = 0.f;
#pragma unroll
    for (int i = 0; i < 8; i++) {
        int k = tid + i * 128;
        float qv = g_qp[0][b * Hd + k] + g_qp[1][b * Hd + k]
                 + g_qp[2][b * Hd + k] + g_qp[3][b * Hd + k] + ba[k];
        acc += tanhf(qv + kr[k]) * Va[k];
    }
#pragma unroll
    for (int o = 16; o; o >>= 1) acc += __shfl_xor_sync(0xffffffffu, acc, o);

    __shared__ float red[4];
    const int wid = tid >> 5, lane = tid & 31;
    if (lane == 0) red[wid] = acc;
    __syncthreads();
    if (tid == 0)
        g_sc[b * Ss + s] = red[0] + red[1] + red[2] + red[3] + bv[0];
}

// ====== ctx: softmax (recomputed per block) + context + embedding gather ===
__global__ void __launch_bounds__(128)
ctx_k(const float* __restrict__ enc, const float* __restrict__ emb,
      const int* __restrict__ target, float* __restrict__ out_attn, int t)
{
    const int b = blockIdx.x, hc = blockIdx.y;
    const int tid = threadIdx.x;
    __shared__ float w[Ss];

    if (tid < Ss) w[tid] = g_sc[b * Ss + tid];
    __syncthreads();
    if (tid < 32) {
        float v0 = w[tid], v1 = w[tid + 32];
        float m = fmaxf(v0, v1);
#pragma unroll
        for (int o = 16; o; o >>= 1) m = fmaxf(m, __shfl_xor_sync(0xffffffffu, m, o));
        float e0 = __expf(v0 - m), e1 = __expf(v1 - m);
        float sum = e0 + e1;
#pragma unroll
        for (int o = 16; o; o >>= 1) sum += __shfl_xor_sync(0xffffffffu, sum, o);
        float inv = 1.f / sum;
        w[tid] = e0 * inv; w[tid + 32] = e1 * inv;
    }
    __syncthreads();

    if (hc == 0 && tid < Ss) out_attn[((size_t)b * Tt + t) * Ss + tid] = w[tid];

    const int h = hc * 128 + tid;
    float acc = 0.f;
#pragma unroll 8
    for (int s = 0; s < Ss; s++)
        acc += w[s] * enc[((size_t)(b * Ss + s)) * Hd + h];
    g_xi[b * 2 * Hd + Hd + h] = acc;

    int tok = (t == 0) ? SOS_TOK : target[b * Tt + (t - 1)];
    g_xi[b * 2 * Hd + h] = emb[(size_t)tok * Hd + h];
}

// ====== cell: reduce gate partials + bias, LSTM, LayerNorm -> bf16 nh =====
__device__ __forceinline__ float sigmoidf_(float x) { return 1.f / (1.f + expf(-x)); }

__global__ void __launch_bounds__(256)
cell_k(const float* __restrict__ b_ih, const float* __restrict__ b_hh,
       const float* __restrict__ ln_g, const float* __restrict__ ln_b, int t)
{
    const int b = blockIdx.x, tid = threadIdx.x;
    const int wid = tid >> 5, lane = tid & 31;
    __shared__ float r1[8], r2[8];

    float hv[4];
    float s1 = 0.f, s2 = 0.f;
#pragma unroll
    for (int i = 0; i < 4; i++) {
        int j = tid + i * 256;
        float vi = b_ih[j] + b_hh[j];
        float vf = b_ih[Hd + j] + b_hh[Hd + j];
        float vg = b_ih[2 * Hd + j] + b_hh[2 * Hd + j];
        float vo = b_ih[3 * Hd + j] + b_hh[3 * Hd + j];
#pragma unroll
        for (int s = 0; s < 6; s++) {
            const float* gp = g_gp[s] + (size_t)b * 4 * Hd;
            vi += gp[j]; vf += gp[Hd + j]; vg += gp[2 * Hd + j]; vo += gp[3 * Hd + j];
        }
        float cv = sigmoidf_(vf) * g_c[b * Hd + j] + sigmoidf_(vi) * tanhf(vg);
        g_c[b * Hd + j] = cv;
        float hh = sigmoidf_(vo) * tanhf(cv);
        g_h[b * Hd + j] = hh;
        hv[i] = hh; s1 += hh; s2 += hh * hh;
    }
#pragma unroll
    for (int o = 16; o; o >>= 1) {
        s1 += __shfl_xor_sync(0xffffffffu, s1, o);
        s2 += __shfl_xor_sync(0xffffffffu, s2, o);
    }
    if (lane == 0) { r1[wid] = s1; r2[wid] = s2; }
    __syncthreads();
    if (wid == 0) {
        float a = (lane < 8) ? r1[lane] : 0.f;
        float q = (lane < 8) ? r2[lane] : 0.f;
#pragma unroll
        for (int o = 4; o; o >>= 1) {
            a += __shfl_xor_sync(0xffffffffu, a, o);
            q += __shfl_xor_sync(0xffffffffu, q, o);
        }
        if (lane == 0) { r1[0] = a; r2[0] = q; }
    }
    __syncthreads();
    float mu  = r1[0] * (1.f / Hd);
    float var = r2[0] * (1.f / Hd) - mu * mu;
    float inv = rsqrtf(var + 1e-5f);
#pragma unroll
    for (int i = 0; i < 4; i++) {
        int j = tid + i * 256;
        float nhv = (hv[i] - mu) * inv * ln_g[j] + ln_b[j];
        g_nhb[((size_t)t * Bb + b) * Hd + j] = __float2bfloat16(nhv);
    }
}

// ================= big logits GEMM: 128x128 tiles, cp.async + ldmatrix ====
__global__ void __launch_bounds__(256)
logits_gemm(const __nv_bfloat16* __restrict__ A, const __nv_bfloat16* __restrict__ Bw,
            const float* __restrict__ bias, float* __restrict__ out)
{
    __shared__ __nv_bfloat16 As[2][128][40];
    __shared__ __nv_bfloat16 Bs[2][128][40];

    const int tid = threadIdx.x;
    const int wid = tid >> 5, lane = tid & 31;
    const int wm = wid & 1, wn = wid >> 1;           // 2 x 4 warps; warp tile 64m x 32n
    const int g  = lane >> 2, tg = lane & 3;
    const int m0 = blockIdx.y * 128, n0 = blockIdx.x * 128;

    const uint32_t sA = (uint32_t)__cvta_generic_to_shared(&As[0][0][0]);
    const uint32_t sB = (uint32_t)__cvta_generic_to_shared(&Bs[0][0][0]);

    float acc[4][4][4];
#pragma unroll
    for (int a = 0; a < 4; a++)
#pragma unroll
        for (int b = 0; b < 4; b++)
#pragma unroll
            for (int c = 0; c < 4; c++) acc[a][b][c] = 0.f;

    // stage loader: 128 rows x 32 cols bf16 per operand, 16B per cp.async
    const int idx0 = tid, idx1 = tid + 256;
    const int r0 = idx0 >> 2, c0 = (idx0 & 3) * 8;
    const int r1 = idx1 >> 2, c1 = (idx1 & 3) * 8;

#define LOAD_STAGE(st, k0)                                                          \
    {                                                                               \
        uint32_t da0 = sA + (uint32_t)((st) * 10240 + r0 * 80 + c0 * 2);            \
        uint32_t da1 = sA + (uint32_t)((st) * 10240 + r1 * 80 + c1 * 2);            \
        uint32_t db0 = sB + (uint32_t)((st) * 10240 + r0 * 80 + c0 * 2);            \
        uint32_t db1 = sB + (uint32_t)((st) * 10240 + r1 * 80 + c1 * 2);            \
        const __nv_bfloat16* sa0 = A + (size_t)(m0 + r0) * Hd + (k0) + c0;          \
        const __nv_bfloat16* sa1 = A + (size_t)(m0 + r1) * Hd + (k0) + c1;          \
        const __nv_bfloat16* sb0 = Bw + (size_t)(n0 + r0) * Hd + (k0) + c0;         \
        const __nv_bfloat16* sb1 = Bw + (size_t)(n0 + r1) * Hd + (k0) + c1;         \
        asm volatile("cp.async.cg.shared.global [%0], [%1], 16;\n" ::"r"(da0), "l"(sa0)); \
        asm volatile("cp.async.cg.shared.global [%0], [%1], 16;\n" ::"r"(da1), "l"(sa1)); \
        asm volatile("cp.async.cg.shared.global [%0], [%1], 16;\n" ::"r"(db0), "l"(sb0)); \
        asm volatile("cp.async.cg.shared.global [%0], [%1], 16;\n" ::"r"(db1), "l"(sb1)); \
    }

    LOAD_STAGE(0, 0)
    asm volatile("cp.async.commit_group;\n" ::: "memory");

    const int qm = lane >> 3, lr = lane & 7;   // ldmatrix lane mapping

    int cur = 0;
#pragma unroll 1
    for (int k0 = 0; k0 < Hd; k0 += 32) {
        asm volatile("cp.async.wait_group 0;\n" ::: "memory");
        __syncthreads();
        if (k0 + 32 < Hd) {
            LOAD_STAGE(cur ^ 1, k0 + 32)
            asm volatile("cp.async.commit_group;\n" ::: "memory");
        }

#pragma unroll
        for (int ki = 0; ki < 2; ++ki) {
            const int kb = ki * 16;
            uint32_t af[4][4], bf[4][2];
#pragma unroll
            for (int mi = 0; mi < 4; mi++) {
                int rr = wm * 64 + mi * 16;
                uint32_t addr = sA + (uint32_t)(cur * 10240
                              + (rr + lr + (qm & 1) * 8) * 80
                              + (kb + (qm >> 1) * 8) * 2);
                asm volatile("ldmatrix.sync.aligned.m8n8.x4.shared.b16 {%0,%1,%2,%3}, [%4];"
                             : "=r"(af[mi][0]), "=r"(af[mi][1]), "=r"(af[mi][2]), "=r"(af[mi][3])
                             : "r"(addr));
            }
#pragma unroll
            for (int np = 0; np < 2; np++) {
                int nr = wn * 32 + np * 16;
                uint32_t addr = sB + (uint32_t)(cur * 10240
                              + (nr + lr + (qm >> 1) * 8) * 80
                              + (kb + (qm & 1) * 8) * 2);
                uint32_t t0, t1, t2, t3;
                asm volatile("ldmatrix.sync.aligned.m8n8.x4.shared.b16 {%0,%1,%2,%3}, [%4];"
                             : "=r"(t0), "=r"(t1), "=r"(t2), "=r"(t3)
                             : "r"(addr));
                bf[np * 2][0] = t0; bf[np * 2][1] = t1;
                bf[np * 2 + 1][0] = t2; bf[np * 2 + 1][1] = t3;
            }
#pragma unroll
            for (int mi = 0; mi < 4; mi++)
#pragma unroll
                for (int ni = 0; ni < 4; ni++)
                    mma16816(acc[mi][ni], af[mi], bf[ni]);
        }
        __syncthreads();
        cur ^= 1;
    }

    // epilogue: bias + remap (row = t*64+b -> b*13+t) + bounds
#pragma unroll
    for (int mi = 0; mi < 4; mi++)
#pragma unroll
        for (int half = 0; half < 2; ++half) {
            int row = m0 + wm * 64 + mi * 16 + g + half * 8;
            if (row < Tt * Bb) {
                size_t orow = (size_t)(row & 63) * Tt + (row >> 6);
#pragma unroll
                for (int ni = 0; ni < 4; ni++) {
                    int col = n0 + wn * 32 + ni * 8 + 2 * tg;
                    float2 v;
                    v.x = acc[mi][ni][half * 2 + 0] + bias[col];
                    v.y = acc[mi][ni][half * 2 + 1] + bias[col + 1];
                    *(float2*)(out + orow * (size_t)Vv + col) = v;
                }
            }
        }
#undef LOAD_STAGE
}

// ---------------- outW fp32 -> bf16 --------------------------------------
__global__ void __launch_bounds__(256)
convW(const float* __restrict__ W)
{
    size_t i = (size_t)blockIdx.x * 256 + threadIdx.x;   // float4 index
    if (i < ((size_t)Vv * Hd) / 4) {
        float4 v = ((const float4*)W)[i];
        __nv_bfloat162* d = (__nv_bfloat162*)g_outWb;
        d[i * 2]     = __floats2bfloat162_rn(v.x, v.y);
        d[i * 2 + 1] = __floats2bfloat162_rn(v.z, v.w);
    }
}

// ---------------- log-softmax in place over V ----------------------------
__global__ void __launch_bounds__(256)
logsoftmax(float* __restrict__ out)
{
    const size_t base = (size_t)blockIdx.x * Vv;
    const int tid = threadIdx.x;
    const int wid = tid >> 5, lane = tid & 31;
    __shared__ float red[9];

    float m = -1e30f;
    for (int i = tid; i < Vv; i += 256) m = fmaxf(m, out[base + i]);
#pragma unroll
    for (int o = 16; o; o >>= 1) m = fmaxf(m, __shfl_xor_sync(0xffffffffu, m, o));
    if (lane == 0) red[wid] = m;
    __syncthreads();
    if (wid == 0) {
        float mm = (lane < 8) ? red[lane] : -1e30f;
#pragma unroll
        for (int o = 4; o; o >>= 1) mm = fmaxf(mm, __shfl_xor_sync(0xffffffffu, mm, o));
        if (lane == 0) red[8] = mm;
    }
    __syncthreads();
    m = red[8];
    __syncthreads();

    float s = 0.f;
    for (int i = tid; i < Vv; i += 256) s += __expf(out[base + i] - m);
#pragma unroll
    for (int o = 16; o; o >>= 1) s += __shfl_xor_sync(0xffffffffu, s, o);
    if (lane == 0) red[wid] = s;
    __syncthreads();
    if (wid == 0) {
        float ss = (lane < 8) ? red[lane] : 0.f;
#pragma unroll
        for (int o = 4; o; o >>= 1) ss += __shfl_xor_sync(0xffffffffu, ss, o);
        if (lane == 0) red[8] = ss;
    }
    __syncthreads();
    float lse = m + logf(red[8]);
    for (int i = tid; i < Vv; i += 256) out[base + i] -= lse;
}

// ---------------- state init / final copies ------------------------------
__global__ void init_state(const float* __restrict__ h0, const float* __restrict__ c0)
{
    int i = blockIdx.x * blockDim.x + threadIdx.x;
    if (i < Bb * Hd) { g_h[i] = h0[i]; g_c[i] = c0[i]; }
    if (i < (896 - Tt * Bb) * Hd)   // zero nhb padding rows 832..895
        g_nhb[(size_t)(Tt * Bb) * Hd + i] = __float2bfloat16(0.f);
}

__global__ void copy_hc(float* __restrict__ out)
{
    int i = blockIdx.x * blockDim.x + threadIdx.x;
    if (i < Bb * Hd) {
        out[(size_t)Bb * Tt * Vv + i] = g_h[i];
        out[(size_t)Bb * Tt * Vv + (size_t)Bb * Hd + i] = g_c[i];
    }
}

// ---------------- launch ---------------------------------------------------
extern "C" void kernel_launch(void* const* d_in, const int* in_sizes, int n_in,
                              void* d_out, int out_size)
{
    (void)in_sizes; (void)n_in; (void)out_size;
    const float* enc    = (const float*)d_in[0];
    const float* enc_h  = (const float*)d_in[1];
    const float* enc_c  = (const float*)d_in[2];
    const int*   target = (const int*)  d_in[3];
    const float* emb    = (const float*)d_in[4];
    const float* Wa     = (const float*)d_in[5];
    const float* ba     = (const float*)d_in[6];
    const float* Ua     = (const float*)d_in[7];
    const float* bu     = (const float*)d_in[8];
    const float* Va     = (const float*)d_in[9];
    const float* bv     = (const float*)d_in[10];
    const float* W_ih   = (const float*)d_in[11];
    const float* W_hh   = (const float*)d_in[12];
    const float* b_ih   = (const float*)d_in[13];
    const float* b_hh   = (const float*)d_in[14];
    const float* ln_g   = (const float*)d_in[15];
    const float* ln_b   = (const float*)d_in[16];
    const float* outW   = (const float*)d_in[17];
    const float* outb   = (const float*)d_in[18];
    float* out = (float*)d_out;

    float *keys, *h, *xi, *qp, *gp;
    __nv_bfloat16 *nhb, *outWb;
    cudaGetSymbolAddress((void**)&keys,  g_keys);
    cudaGetSymbolAddress((void**)&h,     g_h);
    cudaGetSymbolAddress((void**)&xi,    g_xi);
    cudaGetSymbolAddress((void**)&qp,    g_qp);
    cudaGetSymbolAddress((void**)&gp,    g_gp);
    cudaGetSymbolAddress((void**)&nhb,   g_nhb);
    cudaGetSymbolAddress((void**)&outWb, g_outWb);

    float* out_attn = out + (size_t)Bb * Tt * Vv + 2 * (size_t)Bb * Hd;

    init_state<<<(Bb * Hd + 511) / 512, 512>>>(enc_h, enc_c);
    convW<<<(int)(((size_t)Vv * Hd / 4 + 255) / 256), 256>>>(outW);

    // keys_proj = enc @ Ua^T + bu   [4096,1024]
    keys_gemm<<<dim3(Hd / 64, (Bb * Ss) / 64), 128>>>(enc, Ua, keys, bu);

    for (int t = 0; t < Tt; t++) {
        // q partials: h @ Wa^T, 4 k-slices of 256
        splitk_gemm<<<dim3(Hd / 64, 4), 128>>>(
            h, Wa, Hd, 4, nullptr, nullptr, 0, 256, Hd, qp);
        // scores (reduces q partials + ba inline)
        scores_k<<<dim3(Bb, Ss), 128>>>(Va, ba, bv);
        // softmax + ctx + attn write + embedding gather
        ctx_k<<<dim3(Bb, Hd / 128), 128>>>(enc, emb, target, out_attn, t);
        // gates partials: slices 0-3 = xi@W_ih^T (K=2048), 4-5 = h@W_hh^T (K=1024)
        splitk_gemm<<<dim3(4 * Hd / 64, 6), 128>>>(
            xi, W_ih, 2 * Hd, 4, h, W_hh, Hd, 512, 4 * Hd, gp);
        // reduce partials + LSTM + LayerNorm -> bf16 nh
        cell_k<<<Bb, 256>>>(b_ih, b_hh, ln_g, ln_b, t);
    }

    // batched output projection (bf16 A/B), row remap into d_out
    logits_gemm<<<dim3(Vv / 128, 7), 256>>>(nhb, outWb, outb, out);

    logsoftmax<<<Tt * Bb, 256>>>(out);
    copy_hc<<<(Bb * Hd + 511) / 512, 512>>>(out);
}

// round 4
// speedup vs baseline: 3.5137x; 1.2798x over previous
#include <cuda_runtime.h>
#include <cuda_bf16.h>
#include <cstdint>

#define Hd 1024
#define Vv 32000
#define Bb 64
#define Ss 64
#define Tt 13
#define SOS_TOK 2
#define NB5 5120   // W_hh rows (4096) + Wa rows (1024)

// ---------------- static scratch ------------------------------------------
__device__ float g_keys[Bb * Ss * Hd];
__device__ float g_h[Bb * Hd];
__device__ float g_c[Bb * Hd];
__device__ float g_sc[Bb * Ss];
__device__ float g_hp[2][Bb * NB5];          // h@[W_hh|Wa]^T partials
__device__ float g_cp[2][Bb * 4096];         // ctx@W_ihc^T partials
__device__ float g_xpre[896 * 4096];         // x@W_ihx^T + b_ih + b_hh (all steps)

__device__ __nv_bfloat16 g_hHi[Bb * Hd],      g_hLo[Bb * Hd];
__device__ __nv_bfloat16 g_ctxHi[Bb * Hd],    g_ctxLo[Bb * Hd];
__device__ __nv_bfloat16 g_encHi[Bb * Ss * Hd], g_encLo[Bb * Ss * Hd];
__device__ __nv_bfloat16 g_UaHi[Hd * Hd],     g_UaLo[Hd * Hd];
__device__ __nv_bfloat16 g_BhHi[NB5 * Hd],    g_BhLo[NB5 * Hd];       // [W_hh;Wa]
__device__ __nv_bfloat16 g_WxHi[4096 * Hd],   g_WxLo[4096 * Hd];      // W_ih x-cols
__device__ __nv_bfloat16 g_WcHi[4096 * Hd],   g_WcLo[4096 * Hd];      // W_ih ctx-cols
__device__ __nv_bfloat16 g_xgHi[896 * Hd],    g_xgLo[896 * Hd];       // gathered emb
__device__ __nv_bfloat16 g_nhb[896 * Hd];
__device__ __nv_bfloat16 g_outWb[(size_t)Vv * Hd];

// ---------------- mma helper ---------------------------------------------
__device__ __forceinline__ void mma16816(float* d, const uint32_t* a, const uint32_t* b) {
    asm volatile(
        "mma.sync.aligned.m16n8k16.row.col.f32.bf16.bf16.f32 "
        "{%0,%1,%2,%3}, {%4,%5,%6,%7}, {%8,%9}, {%0,%1,%2,%3};\n"
        : "+f"(d[0]), "+f"(d[1]), "+f"(d[2]), "+f"(d[3])
        : "r"(a[0]), "r"(a[1]), "r"(a[2]), "r"(a[3]), "r"(b[0]), "r"(b[1]));
}

// ================= recurrence GEMM: preconverted hi/lo planes =============
// C[M,N] partial/final = A[64(m0+),K] @ B[N,K]^T, split-bf16 (3 mma).
// MODE 0: write fp32 partials at C + slice*64*N (grid.y = #slices, kw each).
// MODE 1: full K (grid.y=1, kw=K), add bias1(+bias2), write C[m0+r][N].
// 128 threads. Block tile 64m x 64n, k-chunk 32, double-buffered cp.async.
template<int MODE>
__global__ void __launch_bounds__(128)
rgemm(const __nv_bfloat16* __restrict__ Ahi, const __nv_bfloat16* __restrict__ Alo,
      const __nv_bfloat16* __restrict__ Bhi, const __nv_bfloat16* __restrict__ Blo,
      int K, int kw, int N, float* __restrict__ C,
      const float* __restrict__ bias1, const float* __restrict__ bias2)
{
    __shared__ __nv_bfloat16 sm[2 * 4 * 64 * 40];   // [stage][plane][64][40]

    const int tid = threadIdx.x;
    const int wid = tid >> 5, lane = tid & 31;
    const int g = lane >> 2, tg = lane & 3;
    const int qm = lane >> 3, lr = lane & 7;
    const int m0 = blockIdx.z * 64;
    const int n0 = blockIdx.x * 64;
    const int slice = blockIdx.y;
    const int kb0 = slice * kw;
    const uint32_t smb = (uint32_t)__cvta_generic_to_shared(sm);
    // strides (bytes): stage 20480, plane 5120, row 80

    float acc[4][2][4];
#pragma unroll
    for (int a = 0; a < 4; a++)
#pragma unroll
        for (int b = 0; b < 2; b++)
#pragma unroll
            for (int c = 0; c < 4; c++) acc[a][b][c] = 0.f;

#define RLOAD(st, k0)                                                              \
    {                                                                              \
        _Pragma("unroll")                                                          \
        for (int p = 0; p < 4; ++p) {                                              \
            const __nv_bfloat16* src = (p == 0) ? Ahi : (p == 1) ? Alo             \
                                      : (p == 2) ? Bhi : Blo;                      \
            const int rbase = (p < 2) ? m0 : n0;                                   \
            _Pragma("unroll")                                                      \
            for (int rep = 0; rep < 2; ++rep) {                                    \
                int idx = tid + rep * 128;                                         \
                int row = idx >> 2, c8 = (idx & 3) * 8;                            \
                uint32_t dst = smb + (uint32_t)((st) * 20480 + p * 5120            \
                                                + row * 80 + c8 * 2);              \
                const __nv_bfloat16* sp = src + (size_t)(rbase + row) * K          \
                                          + (k0) + c8;                             \
                asm volatile("cp.async.cg.shared.global [%0], [%1], 16;\n"         \
                             ::"r"(dst), "l"(sp));                                 \
            }                                                                      \
        }                                                                          \
    }

    RLOAD(0, kb0)
    asm volatile("cp.async.commit_group;\n" ::: "memory");

    int cur = 0;
#pragma unroll 1
    for (int k0 = kb0; k0 < kb0 + kw; k0 += 32) {
        asm volatile("cp.async.wait_group 0;\n" ::: "memory");
        __syncthreads();
        if (k0 + 32 < kb0 + kw) {
            RLOAD(cur ^ 1, k0 + 32)
            asm volatile("cp.async.commit_group;\n" ::: "memory");
        }

#pragma unroll
        for (int ki = 0; ki < 2; ++ki) {
            const int kb = ki * 16;
            uint32_t ah[4][4], al[4][4], bh[2][2], bl[2][2];
#pragma unroll
            for (int mi = 0; mi < 4; mi++) {
                uint32_t adr = smb + (uint32_t)(cur * 20480
                             + (mi * 16 + lr + (qm & 1) * 8) * 80
                             + (kb + (qm >> 1) * 8) * 2);
                asm volatile("ldmatrix.sync.aligned.m8n8.x4.shared.b16 {%0,%1,%2,%3}, [%4];"
                             : "=r"(ah[mi][0]), "=r"(ah[mi][1]), "=r"(ah[mi][2]), "=r"(ah[mi][3])
                             : "r"(adr));
                asm volatile("ldmatrix.sync.aligned.m8n8.x4.shared.b16 {%0,%1,%2,%3}, [%4];"
                             : "=r"(al[mi][0]), "=r"(al[mi][1]), "=r"(al[mi][2]), "=r"(al[mi][3])
                             : "r"(adr + 5120));
            }
            {
                uint32_t adr = smb + (uint32_t)(cur * 20480 + 2 * 5120
                             + (wid * 16 + lr + (qm >> 1) * 8) * 80
                             + (kb + (qm & 1) * 8) * 2);
                uint32_t t0, t1, t2, t3;
                asm volatile("ldmatrix.sync.aligned.m8n8.x4.shared.b16 {%0,%1,%2,%3}, [%4];"
                             : "=r"(t0), "=r"(t1), "=r"(t2), "=r"(t3) : "r"(adr));
                bh[0][0] = t0; bh[0][1] = t1; bh[1][0] = t2; bh[1][1] = t3;
                asm volatile("ldmatrix.sync.aligned.m8n8.x4.shared.b16 {%0,%1,%2,%3}, [%4];"
                             : "=r"(t0), "=r"(t1), "=r"(t2), "=r"(t3) : "r"(adr + 5120));
                bl[0][0] = t0; bl[0][1] = t1; bl[1][0] = t2; bl[1][1] = t3;
            }
#pragma unroll
            for (int mi = 0; mi < 4; mi++)
#pragma unroll
                for (int ni = 0; ni < 2; ni++) {
                    mma16816(acc[mi][ni], ah[mi], bh[ni]);
                    mma16816(acc[mi][ni], ah[mi], bl[ni]);
                    mma16816(acc[mi][ni], al[mi], bh[ni]);
                }
        }
        __syncthreads();
        cur ^= 1;
    }
#undef RLOAD

#pragma unroll
    for (int mi = 0; mi < 4; mi++)
#pragma unroll
        for (int half = 0; half < 2; ++half) {
            int r = mi * 16 + g + half * 8;
#pragma unroll
            for (int ni = 0; ni < 2; ni++) {
                int col = n0 + wid * 16 + ni * 8 + 2 * tg;
                float2 v;
                v.x = acc[mi][ni][half * 2 + 0];
                v.y = acc[mi][ni][half * 2 + 1];
                if (MODE == 1) {
                    v.x += bias1[col];     v.y += bias1[col + 1];
                    if (bias2) { v.x += bias2[col]; v.y += bias2[col + 1]; }
                    *(float2*)(C + (size_t)(m0 + r) * N + col) = v;
                } else {
                    *(float2*)(C + (size_t)slice * 64 * N + (size_t)r * N + col) = v;
                }
            }
        }
}

// ================= fp32 -> hi/lo bf16 plane conversion ====================
__global__ void __launch_bounds__(256)
conv_planes(const float* __restrict__ src, int lds, int coff,
            __nv_bfloat16* __restrict__ hi, __nv_bfloat16* __restrict__ lo,
            size_t total, int K)
{
    for (size_t i = (size_t)blockIdx.x * 256 + threadIdx.x; i < total;
         i += (size_t)gridDim.x * 256) {
        size_t row = i / (size_t)K;
        int col = (int)(i - row * K);
        float v = src[row * (size_t)lds + coff + col];
        __nv_bfloat16 h = __float2bfloat16(v);
        hi[i] = h;
        lo[i] = __float2bfloat16(v - __bfloat162float(h));
    }
}

// ================= embedding gather for all steps ========================
__global__ void __launch_bounds__(256)
gather_x(const float* __restrict__ emb, const int* __restrict__ target)
{
    for (size_t i = (size_t)blockIdx.x * 256 + threadIdx.x; i < (size_t)896 * Hd;
         i += (size_t)gridDim.x * 256) {
        int r = (int)(i >> 10), k = (int)(i & 1023);
        float v = 0.f;
        if (r < Tt * Bb) {
            int t = r >> 6, b = r & 63;
            int tok = (t == 0) ? SOS_TOK : target[b * Tt + (t - 1)];
            v = emb[(size_t)tok * Hd + k];
        }
        __nv_bfloat16 h = __float2bfloat16(v);
        g_xgHi[i] = h;
        g_xgLo[i] = __float2bfloat16(v - __bfloat162float(h));
    }
}

// ================= scores: one block per (b, s) ==========================
__global__ void __launch_bounds__(128)
scores_k(const float* __restrict__ Va, const float* __restrict__ ba,
         const float* __restrict__ bv)
{
    const int b = blockIdx.x, s = blockIdx.y;
    const int tid = threadIdx.x;
    const float* kr = g_keys + ((size_t)(b * Ss + s)) * Hd;

    float acc = 0.f;
#pragma unroll
    for (int i = 0; i < 8; i++) {
        int k = tid + i * 128;
        float qv = g_hp[0][b * NB5 + 4096 + k] + g_hp[1][b * NB5 + 4096 + k] + ba[k];
        acc += tanhf(qv + kr[k]) * Va[k];
    }
#pragma unroll
    for (int o = 16; o; o >>= 1) acc += __shfl_xor_sync(0xffffffffu, acc, o);

    __shared__ float red[4];
    const int wid = tid >> 5, lane = tid & 31;
    if (lane == 0) red[wid] = acc;
    __syncthreads();
    if (tid == 0)
        g_sc[b * Ss + s] = red[0] + red[1] + red[2] + red[3] + bv[0];
}

// ====== ctx: softmax + context -> hi/lo planes + attn write ===============
__global__ void __launch_bounds__(128)
ctx_k(const float* __restrict__ enc, float* __restrict__ out_attn, int t)
{
    const int b = blockIdx.x, hc = blockIdx.y;
    const int tid = threadIdx.x;
    __shared__ float w[Ss];

    if (tid < Ss) w[tid] = g_sc[b * Ss + tid];
    __syncthreads();
    if (tid < 32) {
        float v0 = w[tid], v1 = w[tid + 32];
        float m = fmaxf(v0, v1);
#pragma unroll
        for (int o = 16; o; o >>= 1) m = fmaxf(m, __shfl_xor_sync(0xffffffffu, m, o));
        float e0 = __expf(v0 - m), e1 = __expf(v1 - m);
        float sum = e0 + e1;
#pragma unroll
        for (int o = 16; o; o >>= 1) sum += __shfl_xor_sync(0xffffffffu, sum, o);
        float inv = 1.f / sum;
        w[tid] = e0 * inv; w[tid + 32] = e1 * inv;
    }
    __syncthreads();

    if (hc == 0 && tid < Ss) out_attn[((size_t)b * Tt + t) * Ss + tid] = w[tid];

    const int h = hc * 128 + tid;
    float acc = 0.f;
#pragma unroll 8
    for (int s = 0; s < Ss; s++)
        acc += w[s] * enc[((size_t)(b * Ss + s)) * Hd + h];
    __nv_bfloat16 chi = __float2bfloat16(acc);
    g_ctxHi[b * Hd + h] = chi;
    g_ctxLo[b * Hd + h] = __float2bfloat16(acc - __bfloat162float(chi));
}

// ====== cell: gates = xpre + hp + cp ; LSTM ; LayerNorm -> bf16 nh ========
__device__ __forceinline__ float sigmoidf_(float x) { return 1.f / (1.f + expf(-x)); }

__global__ void __launch_bounds__(256)
cell_k(const float* __restrict__ ln_g, const float* __restrict__ ln_b, int t)
{
    const int b = blockIdx.x, tid = threadIdx.x;
    const int wid = tid >> 5, lane = tid & 31;
    __shared__ float r1[8], r2[8];
    const size_t xr = (size_t)(t * Bb + b) * 4096;

    float hv[4];
    float s1 = 0.f, s2 = 0.f;
#pragma unroll
    for (int i = 0; i < 4; i++) {
        int j = tid + i * 256;
        float vi = g_xpre[xr + j]          + g_hp[0][b * NB5 + j]          + g_hp[1][b * NB5 + j]
                 + g_cp[0][b * 4096 + j]   + g_cp[1][b * 4096 + j];
        float vf = g_xpre[xr + Hd + j]     + g_hp[0][b * NB5 + Hd + j]     + g_hp[1][b * NB5 + Hd + j]
                 + g_cp[0][b * 4096 + Hd + j] + g_cp[1][b * 4096 + Hd + j];
        float vg = g_xpre[xr + 2 * Hd + j] + g_hp[0][b * NB5 + 2 * Hd + j] + g_hp[1][b * NB5 + 2 * Hd + j]
                 + g_cp[0][b * 4096 + 2 * Hd + j] + g_cp[1][b * 4096 + 2 * Hd + j];
        float vo = g_xpre[xr + 3 * Hd + j] + g_hp[0][b * NB5 + 3 * Hd + j] + g_hp[1][b * NB5 + 3 * Hd + j]
                 + g_cp[0][b * 4096 + 3 * Hd + j] + g_cp[1][b * 4096 + 3 * Hd + j];
        float cv = sigmoidf_(vf) * g_c[b * Hd + j] + sigmoidf_(vi) * tanhf(vg);
        g_c[b * Hd + j] = cv;
        float hh = sigmoidf_(vo) * tanhf(cv);
        g_h[b * Hd + j] = hh;
        __nv_bfloat16 hb = __float2bfloat16(hh);
        g_hHi[b * Hd + j] = hb;
        g_hLo[b * Hd + j] = __float2bfloat16(hh - __bfloat162float(hb));
        hv[i] = hh; s1 += hh; s2 += hh * hh;
    }
#pragma unroll
    for (int o = 16; o; o >>= 1) {
        s1 += __shfl_xor_sync(0xffffffffu, s1, o);
        s2 += __shfl_xor_sync(0xffffffffu, s2, o);
    }
    if (lane == 0) { r1[wid] = s1; r2[wid] = s2; }
    __syncthreads();
    if (wid == 0) {
        float a = (lane < 8) ? r1[lane] : 0.f;
        float q = (lane < 8) ? r2[lane] : 0.f;
#pragma unroll
        for (int o = 4; o; o >>= 1) {
            a += __shfl_xor_sync(0xffffffffu, a, o);
            q += __shfl_xor_sync(0xffffffffu, q, o);
        }
        if (lane == 0) { r1[0] = a; r2[0] = q; }
    }
    __syncthreads();
    float mu  = r1[0] * (1.f / Hd);
    float var = r2[0] * (1.f / Hd) - mu * mu;
    float inv = rsqrtf(var + 1e-5f);
#pragma unroll
    for (int i = 0; i < 4; i++) {
        int j = tid + i * 256;
        float nhv = (hv[i] - mu) * inv * ln_g[j] + ln_b[j];
        g_nhb[((size_t)t * Bb + b) * Hd + j] = __float2bfloat16(nhv);
    }
}

// ================= big logits GEMM (unchanged, proven) ====================
__global__ void __launch_bounds__(256)
logits_gemm(const __nv_bfloat16* __restrict__ A, const __nv_bfloat16* __restrict__ Bw,
            const float* __restrict__ bias, float* __restrict__ out)
{
    __shared__ __nv_bfloat16 As[2][128][40];
    __shared__ __nv_bfloat16 Bs[2][128][40];

    const int tid = threadIdx.x;
    const int wid = tid >> 5, lane = tid & 31;
    const int wm = wid & 1, wn = wid >> 1;
    const int g  = lane >> 2, tg = lane & 3;
    const int m0 = blockIdx.y * 128, n0 = blockIdx.x * 128;

    const uint32_t sA = (uint32_t)__cvta_generic_to_shared(&As[0][0][0]);
    const uint32_t sB = (uint32_t)__cvta_generic_to_shared(&Bs[0][0][0]);

    float acc[4][4][4];
#pragma unroll
    for (int a = 0; a < 4; a++)
#pragma unroll
        for (int b = 0; b < 4; b++)
#pragma unroll
            for (int c = 0; c < 4; c++) acc[a][b][c] = 0.f;

    const int idx0 = tid, idx1 = tid + 256;
    const int r0 = idx0 >> 2, c0 = (idx0 & 3) * 8;
    const int r1 = idx1 >> 2, c1 = (idx1 & 3) * 8;

#define LOAD_STAGE(st, k0)                                                          \
    {                                                                               \
        uint32_t da0 = sA + (uint32_t)((st) * 10240 + r0 * 80 + c0 * 2);            \
        uint32_t da1 = sA + (uint32_t)((st) * 10240 + r1 * 80 + c1 * 2);            \
        uint32_t db0 = sB + (uint32_t)((st) * 10240 + r0 * 80 + c0 * 2);            \
        uint32_t db1 = sB + (uint32_t)((st) * 10240 + r1 * 80 + c1 * 2);            \
        const __nv_bfloat16* sa0 = A + (size_t)(m0 + r0) * Hd + (k0) + c0;          \
        const __nv_bfloat16* sa1 = A + (size_t)(m0 + r1) * Hd + (k0) + c1;          \
        const __nv_bfloat16* sb0 = Bw + (size_t)(n0 + r0) * Hd + (k0) + c0;         \
        const __nv_bfloat16* sb1 = Bw + (size_t)(n0 + r1) * Hd + (k0) + c1;         \
        asm volatile("cp.async.cg.shared.global [%0], [%1], 16;\n" ::"r"(da0), "l"(sa0)); \
        asm volatile("cp.async.cg.shared.global [%0], [%1], 16;\n" ::"r"(da1), "l"(sa1)); \
        asm volatile("cp.async.cg.shared.global [%0], [%1], 16;\n" ::"r"(db0), "l"(sb0)); \
        asm volatile("cp.async.cg.shared.global [%0], [%1], 16;\n" ::"r"(db1), "l"(sb1)); \
    }

    LOAD_STAGE(0, 0)
    asm volatile("cp.async.commit_group;\n" ::: "memory");

    const int qm = lane >> 3, lr = lane & 7;

    int cur = 0;
#pragma unroll 1
    for (int k0 = 0; k0 < Hd; k0 += 32) {
        asm volatile("cp.async.wait_group 0;\n" ::: "memory");
        __syncthreads();
        if (k0 + 32 < Hd) {
            LOAD_STAGE(cur ^ 1, k0 + 32)
            asm volatile("cp.async.commit_group;\n" ::: "memory");
        }

#pragma unroll
        for (int ki = 0; ki < 2; ++ki) {
            const int kb = ki * 16;
            uint32_t af[4][4], bf[4][2];
#pragma unroll
            for (int mi = 0; mi < 4; mi++) {
                int rr = wm * 64 + mi * 16;
                uint32_t addr = sA + (uint32_t)(cur * 10240
                              + (rr + lr + (qm & 1) * 8) * 80
                              + (kb + (qm >> 1) * 8) * 2);
                asm volatile("ldmatrix.sync.aligned.m8n8.x4.shared.b16 {%0,%1,%2,%3}, [%4];"
                             : "=r"(af[mi][0]), "=r"(af[mi][1]), "=r"(af[mi][2]), "=r"(af[mi][3])
                             : "r"(addr));
            }
#pragma unroll
            for (int np = 0; np < 2; np++) {
                int nr = wn * 32 + np * 16;
                uint32_t addr = sB + (uint32_t)(cur * 10240
                              + (nr + lr + (qm >> 1) * 8) * 80
                              + (kb + (qm & 1) * 8) * 2);
                uint32_t t0, t1, t2, t3;
                asm volatile("ldmatrix.sync.aligned.m8n8.x4.shared.b16 {%0,%1,%2,%3}, [%4];"
                             : "=r"(t0), "=r"(t1), "=r"(t2), "=r"(t3)
                             : "r"(addr));
                bf[np * 2][0] = t0; bf[np * 2][1] = t1;
                bf[np * 2 + 1][0] = t2; bf[np * 2 + 1][1] = t3;
            }
#pragma unroll
            for (int mi = 0; mi < 4; mi++)
#pragma unroll
                for (int ni = 0; ni < 4; ni++)
                    mma16816(acc[mi][ni], af[mi], bf[ni]);
        }
        __syncthreads();
        cur ^= 1;
    }

#pragma unroll
    for (int mi = 0; mi < 4; mi++)
#pragma unroll
        for (int half = 0; half < 2; ++half) {
            int row = m0 + wm * 64 + mi * 16 + g + half * 8;
            if (row < Tt * Bb) {
                size_t orow = (size_t)(row & 63) * Tt + (row >> 6);
#pragma unroll
                for (int ni = 0; ni < 4; ni++) {
                    int col = n0 + wn * 32 + ni * 8 + 2 * tg;
                    float2 v;
                    v.x = acc[mi][ni][half * 2 + 0] + bias[col];
                    v.y = acc[mi][ni][half * 2 + 1] + bias[col + 1];
                    *(float2*)(out + orow * (size_t)Vv + col) = v;
                }
            }
        }
#undef LOAD_STAGE
}

// ---------------- outW fp32 -> bf16 --------------------------------------
__global__ void __launch_bounds__(256)
convW(const float* __restrict__ W)
{
    size_t i = (size_t)blockIdx.x * 256 + threadIdx.x;
    if (i < ((size_t)Vv * Hd) / 4) {
        float4 v = ((const float4*)W)[i];
        __nv_bfloat162* d = (__nv_bfloat162*)g_outWb;
        d[i * 2]     = __floats2bfloat162_rn(v.x, v.y);
        d[i * 2 + 1] = __floats2bfloat162_rn(v.z, v.w);
    }
}

// ---------------- single-pass online log-softmax --------------------------
__global__ void __launch_bounds__(512)
logsoftmax(float* __restrict__ out)
{
    const size_t base = (size_t)blockIdx.x * Vv;
    const int tid = threadIdx.x;
    const int wid = tid >> 5, lane = tid & 31;
    __shared__ float rm[16], rs[16], fin[2];

    float m = -1e30f, s = 0.f;
    const float4* p = (const float4*)(out + base);
    for (int i = tid; i < Vv / 4; i += 512) {
        float4 v = p[i];
        float xs[4] = {v.x, v.y, v.z, v.w};
#pragma unroll
        for (int e = 0; e < 4; e++) {
            float nm = fmaxf(m, xs[e]);
            s = s * __expf(m - nm) + __expf(xs[e] - nm);
            m = nm;
        }
    }
#pragma unroll
    for (int o = 16; o; o >>= 1) {
        float om = __shfl_xor_sync(0xffffffffu, m, o);
        float os = __shfl_xor_sync(0xffffffffu, s, o);
        float nm = fmaxf(m, om);
        s = s * __expf(m - nm) + os * __expf(om - nm);
        m = nm;
    }
    if (lane == 0) { rm[wid] = m; rs[wid] = s; }
    __syncthreads();
    if (wid == 0) {
        float mm = (lane < 16) ? rm[lane] : -1e30f;
        float ss = (lane < 16) ? rs[lane] : 0.f;
#pragma unroll
        for (int o = 8; o; o >>= 1) {
            float om = __shfl_xor_sync(0xffffffffu, mm, o);
            float os = __shfl_xor_sync(0xffffffffu, ss, o);
            float nm = fmaxf(mm, om);
            ss = ss * __expf(mm - nm) + os * __expf(om - nm);
            mm = nm;
        }
        if (lane == 0) { fin[0] = mm; fin[1] = ss; }
    }
    __syncthreads();
    float lse = fin[0] + logf(fin[1]);
    float4* q = (float4*)(out + base);
    for (int i = tid; i < Vv / 4; i += 512) {
        float4 v = q[i];
        v.x -= lse; v.y -= lse; v.z -= lse; v.w -= lse;
        q[i] = v;
    }
}

// ---------------- state init / final copies ------------------------------
__global__ void init_state(const float* __restrict__ h0, const float* __restrict__ c0)
{
    int i = blockIdx.x * blockDim.x + threadIdx.x;
    if (i < Bb * Hd) {
        float hv = h0[i];
        g_h[i] = hv; g_c[i] = c0[i];
        __nv_bfloat16 hb = __float2bfloat16(hv);
        g_hHi[i] = hb;
        g_hLo[i] = __float2bfloat16(hv - __bfloat162float(hb));
        // zero nhb padding rows (832..895): 64*1024 elems, same index range
        g_nhb[(size_t)(Tt * Bb) * Hd + i] = __float2bfloat16(0.f);
    }
}

__global__ void copy_hc(float* __restrict__ out)
{
    int i = blockIdx.x * blockDim.x + threadIdx.x;
    if (i < Bb * Hd) {
        out[(size_t)Bb * Tt * Vv + i] = g_h[i];
        out[(size_t)Bb * Tt * Vv + (size_t)Bb * Hd + i] = g_c[i];
    }
}

// ---------------- launch ---------------------------------------------------
extern "C" void kernel_launch(void* const* d_in, const int* in_sizes, int n_in,
                              void* d_out, int out_size)
{
    (void)in_sizes; (void)n_in; (void)out_size;
    const float* enc    = (const float*)d_in[0];
    const float* enc_h  = (const float*)d_in[1];
    const float* enc_c  = (const float*)d_in[2];
    const int*   target = (const int*)  d_in[3];
    const float* emb    = (const float*)d_in[4];
    const float* Wa     = (const float*)d_in[5];
    const float* ba     = (const float*)d_in[6];
    const float* Ua     = (const float*)d_in[7];
    const float* bu     = (const float*)d_in[8];
    const float* Va     = (const float*)d_in[9];
    const float* bv     = (const float*)d_in[10];
    const float* W_ih   = (const float*)d_in[11];
    const float* W_hh   = (const float*)d_in[12];
    const float* b_ih   = (const float*)d_in[13];
    const float* b_hh   = (const float*)d_in[14];
    const float* ln_g   = (const float*)d_in[15];
    const float* ln_b   = (const float*)d_in[16];
    const float* outW   = (const float*)d_in[17];
    const float* outb   = (const float*)d_in[18];
    float* out = (float*)d_out;

    float *keys, *hp, *cp, *xpre;
    __nv_bfloat16 *hHi, *hLo, *ctxHi, *ctxLo, *encHi, *encLo, *UaHi, *UaLo;
    __nv_bfloat16 *BhHi, *BhLo, *WxHi, *WxLo, *WcHi, *WcLo, *xgHi, *xgLo;
    __nv_bfloat16 *nhb, *outWb;
    cudaGetSymbolAddress((void**)&keys,  g_keys);
    cudaGetSymbolAddress((void**)&hp,    g_hp);
    cudaGetSymbolAddress((void**)&cp,    g_cp);
    cudaGetSymbolAddress((void**)&xpre,  g_xpre);
    cudaGetSymbolAddress((void**)&hHi,   g_hHi);
    cudaGetSymbolAddress((void**)&hLo,   g_hLo);
    cudaGetSymbolAddress((void**)&ctxHi, g_ctxHi);
    cudaGetSymbolAddress((void**)&ctxLo, g_ctxLo);
    cudaGetSymbolAddress((void**)&encHi, g_encHi);
    cudaGetSymbolAddress((void**)&encLo, g_encLo);
    cudaGetSymbolAddress((void**)&UaHi,  g_UaHi);
    cudaGetSymbolAddress((void**)&UaLo,  g_UaLo);
    cudaGetSymbolAddress((void**)&BhHi,  g_BhHi);
    cudaGetSymbolAddress((void**)&BhLo,  g_BhLo);
    cudaGetSymbolAddress((void**)&WxHi,  g_WxHi);
    cudaGetSymbolAddress((void**)&WxLo,  g_WxLo);
    cudaGetSymbolAddress((void**)&WcHi,  g_WcHi);
    cudaGetSymbolAddress((void**)&WcLo,  g_WcLo);
    cudaGetSymbolAddress((void**)&xgHi,  g_xgHi);
    cudaGetSymbolAddress((void**)&xgLo,  g_xgLo);
    cudaGetSymbolAddress((void**)&nhb,   g_nhb);
    cudaGetSymbolAddress((void**)&outWb, g_outWb);

    float* out_attn = out + (size_t)Bb * Tt * Vv + 2 * (size_t)Bb * Hd;

    init_state<<<(Bb * Hd + 511) / 512, 512>>>(enc_h, enc_c);
    convW<<<(int)(((size_t)Vv * Hd / 4 + 255) / 256), 256>>>(outW);

    // one-time plane conversions
    conv_planes<<<4096, 256>>>(W_hh, Hd, 0,    BhHi, BhLo, (size_t)4096 * Hd, Hd);
    conv_planes<<<2048, 256>>>(Wa,   Hd, 0,    BhHi + (size_t)4096 * Hd,
                                               BhLo + (size_t)4096 * Hd, (size_t)1024 * Hd, Hd);
    conv_planes<<<4096, 256>>>(W_ih, 2 * Hd, 0,   WxHi, WxLo, (size_t)4096 * Hd, Hd);
    conv_planes<<<4096, 256>>>(W_ih, 2 * Hd, Hd,  WcHi, WcLo, (size_t)4096 * Hd, Hd);
    conv_planes<<<2048, 256>>>(Ua,   Hd, 0,    UaHi, UaLo, (size_t)Hd * Hd, Hd);
    conv_planes<<<4096, 256>>>(enc,  Hd, 0,    encHi, encLo, (size_t)Bb * Ss * Hd, Hd);
    gather_x<<<1024, 256>>>(emb, target);

    // xpre = xg @ W_ihx^T + b_ih + b_hh   [896 x 4096]
    rgemm<1><<<dim3(64, 1, 14), 128>>>(xgHi, xgLo, WxHi, WxLo,
                                       Hd, Hd, 4096, xpre, b_ih, b_hh);
    // keys = enc @ Ua^T + bu   [4096 x 1024]
    rgemm<1><<<dim3(16, 1, 64), 128>>>(encHi, encLo, UaHi, UaLo,
                                       Hd, Hd, Hd, keys, bu, nullptr);

    for (int t = 0; t < Tt; t++) {
        // h @ [W_hh | Wa]^T partials  (N=5120, 2 k-slices)
        rgemm<0><<<dim3(80, 2, 1), 128>>>(hHi, hLo, BhHi, BhLo,
                                          Hd, 512, NB5, hp, nullptr, nullptr);
        scores_k<<<dim3(Bb, Ss), 128>>>(Va, ba, bv);
        ctx_k<<<dim3(Bb, Hd / 128), 128>>>(enc, out_attn, t);
        // ctx @ W_ihc^T partials  (N=4096, 2 k-slices)
        rgemm<0><<<dim3(64, 2, 1), 128>>>(ctxHi, ctxLo, WcHi, WcLo,
                                          Hd, 512, 4096, cp, nullptr, nullptr);
        cell_k<<<Bb, 256>>>(ln_g, ln_b, t);
    }

    logits_gemm<<<dim3(Vv / 128, 7), 256>>>(nhb, outWb, outb, out);
    logsoftmax<<<Tt * Bb, 512>>>(out);
    copy_hc<<<(Bb * Hd + 511) / 512, 512>>>(out);
}

// round 5
// speedup vs baseline: 3.8355x; 1.0916x over previous
#include <cuda_runtime.h>
#include <cuda_bf16.h>
#include <cstdint>

#define Hd 1024
#define Vv 32000
#define Bb 64
#define Ss 64
#define Tt 13
#define SOS_TOK 2
#define NB5 5120   // W_hh rows (4096) + Wa rows (1024)

// ---------------- static scratch ------------------------------------------
__device__ float g_keys[Bb * Ss * Hd];
__device__ float g_h[Bb * Hd];
__device__ float g_c[Bb * Hd];
__device__ float g_sc[Bb * Ss];
__device__ float g_hp[4][Bb * NB5];          // h@[W_hh|Wa]^T partials (4 k-slices)
__device__ float g_cp[4][Bb * 4096];         // ctx@W_ihc^T partials
__device__ float g_xpre[896 * 4096];         // x@W_ihx^T + b_ih + b_hh (all steps)

__device__ __nv_bfloat16 g_hHi[Bb * Hd],      g_hLo[Bb * Hd];
__device__ __nv_bfloat16 g_ctxHi[Bb * Hd],    g_ctxLo[Bb * Hd];
__device__ __nv_bfloat16 g_encHi[Bb * Ss * Hd], g_encLo[Bb * Ss * Hd];
__device__ __nv_bfloat16 g_UaHi[Hd * Hd],     g_UaLo[Hd * Hd];
__device__ __nv_bfloat16 g_BhHi[NB5 * Hd],    g_BhLo[NB5 * Hd];       // [W_hh;Wa]
__device__ __nv_bfloat16 g_WxHi[4096 * Hd],   g_WxLo[4096 * Hd];      // W_ih x-cols
__device__ __nv_bfloat16 g_WcHi[4096 * Hd],   g_WcLo[4096 * Hd];      // W_ih ctx-cols
__device__ __nv_bfloat16 g_xgHi[896 * Hd],    g_xgLo[896 * Hd];       // gathered emb
__device__ __nv_bfloat16 g_nhb[896 * Hd];
__device__ __nv_bfloat16 g_outWb[(size_t)Vv * Hd];

// ---------------- math helpers -------------------------------------------
__device__ __forceinline__ float rcp_fast(float d) {
    float r = __int_as_float(0x7EF311C3 - __float_as_int(d));
    r = r * __fmaf_rn(-d, r, 2.0f);
    r = r * __fmaf_rn(-d, r, 2.0f);
    return r;
}
__device__ __forceinline__ float tanh_mufu(float x) {
    float y;
    asm("tanh.approx.f32 %0, %1;" : "=f"(y) : "f"(x));
    return y;
}
// Pade 7/6 tanh, FMA/ALU pipes only (no MUFU). |err| < ~1e-4 with clamp.
__device__ __forceinline__ float tanh_poly(float x) {
    float cx = fminf(fmaxf(x, -4.97f), 4.97f);
    float t = cx * cx;
    float p = t + 378.f;
    p = __fmaf_rn(p, t, 17325.f);
    p = __fmaf_rn(p, t, 135135.f);
    p = p * cx;
    float q = __fmaf_rn(28.f, t, 3150.f);
    q = __fmaf_rn(q, t, 62370.f);
    q = __fmaf_rn(q, t, 135135.f);
    return p * rcp_fast(q);
}
__device__ __forceinline__ float sigmoid_fast(float x) {
    return rcp_fast(1.f + __expf(-x));   // 1 MUFU (EX2) + FMA recip
}

// ---------------- mma helper ---------------------------------------------
__device__ __forceinline__ void mma16816(float* d, const uint32_t* a, const uint32_t* b) {
    asm volatile(
        "mma.sync.aligned.m16n8k16.row.col.f32.bf16.bf16.f32 "
        "{%0,%1,%2,%3}, {%4,%5,%6,%7}, {%8,%9}, {%0,%1,%2,%3};\n"
        : "+f"(d[0]), "+f"(d[1]), "+f"(d[2]), "+f"(d[3])
        : "r"(a[0]), "r"(a[1]), "r"(a[2]), "r"(a[3]), "r"(b[0]), "r"(b[1]));
}

// ================= recurrence GEMM: preconverted hi/lo planes =============
// MODE 0: fp32 partials at C + slice*64*N (grid.y slices of kw).
// MODE 1: full K (grid.y=1, kw=K), + bias1(+bias2), C[m0+r][N].
template<int MODE>
__global__ void __launch_bounds__(128)
rgemm(const __nv_bfloat16* __restrict__ Ahi, const __nv_bfloat16* __restrict__ Alo,
      const __nv_bfloat16* __restrict__ Bhi, const __nv_bfloat16* __restrict__ Blo,
      int K, int kw, int N, float* __restrict__ C,
      const float* __restrict__ bias1, const float* __restrict__ bias2)
{
    __shared__ __nv_bfloat16 sm[2 * 4 * 64 * 40];   // [stage][plane][64][40]

    const int tid = threadIdx.x;
    const int wid = tid >> 5, lane = tid & 31;
    const int g = lane >> 2, tg = lane & 3;
    const int qm = lane >> 3, lr = lane & 7;
    const int m0 = blockIdx.z * 64;
    const int n0 = blockIdx.x * 64;
    const int slice = blockIdx.y;
    const int kb0 = slice * kw;
    const uint32_t smb = (uint32_t)__cvta_generic_to_shared(sm);

    float acc[4][2][4];
#pragma unroll
    for (int a = 0; a < 4; a++)
#pragma unroll
        for (int b = 0; b < 2; b++)
#pragma unroll
            for (int c = 0; c < 4; c++) acc[a][b][c] = 0.f;

#define RLOAD(st, k0)                                                              \
    {                                                                              \
        _Pragma("unroll")                                                          \
        for (int p = 0; p < 4; ++p) {                                              \
            const __nv_bfloat16* src = (p == 0) ? Ahi : (p == 1) ? Alo             \
                                      : (p == 2) ? Bhi : Blo;                      \
            const int rbase = (p < 2) ? m0 : n0;                                   \
            _Pragma("unroll")                                                      \
            for (int rep = 0; rep < 2; ++rep) {                                    \
                int idx = tid + rep * 128;                                         \
                int row = idx >> 2, c8 = (idx & 3) * 8;                            \
                uint32_t dst = smb + (uint32_t)((st) * 20480 + p * 5120            \
                                                + row * 80 + c8 * 2);              \
                const __nv_bfloat16* sp = src + (size_t)(rbase + row) * K          \
                                          + (k0) + c8;                             \
                asm volatile("cp.async.cg.shared.global [%0], [%1], 16;\n"         \
                             ::"r"(dst), "l"(sp));                                 \
            }                                                                      \
        }                                                                          \
    }

    RLOAD(0, kb0)
    asm volatile("cp.async.commit_group;\n" ::: "memory");

    int cur = 0;
#pragma unroll 1
    for (int k0 = kb0; k0 < kb0 + kw; k0 += 32) {
        asm volatile("cp.async.wait_group 0;\n" ::: "memory");
        __syncthreads();
        if (k0 + 32 < kb0 + kw) {
            RLOAD(cur ^ 1, k0 + 32)
            asm volatile("cp.async.commit_group;\n" ::: "memory");
        }

#pragma unroll
        for (int ki = 0; ki < 2; ++ki) {
            const int kb = ki * 16;
            uint32_t ah[4][4], al[4][4], bh[2][2], bl[2][2];
#pragma unroll
            for (int mi = 0; mi < 4; mi++) {
                uint32_t adr = smb + (uint32_t)(cur * 20480
                             + (mi * 16 + lr + (qm & 1) * 8) * 80
                             + (kb + (qm >> 1) * 8) * 2);
                asm volatile("ldmatrix.sync.aligned.m8n8.x4.shared.b16 {%0,%1,%2,%3}, [%4];"
                             : "=r"(ah[mi][0]), "=r"(ah[mi][1]), "=r"(ah[mi][2]), "=r"(ah[mi][3])
                             : "r"(adr));
                asm volatile("ldmatrix.sync.aligned.m8n8.x4.shared.b16 {%0,%1,%2,%3}, [%4];"
                             : "=r"(al[mi][0]), "=r"(al[mi][1]), "=r"(al[mi][2]), "=r"(al[mi][3])
                             : "r"(adr + 5120));
            }
            {
                uint32_t adr = smb + (uint32_t)(cur * 20480 + 2 * 5120
                             + (wid * 16 + lr + (qm >> 1) * 8) * 80
                             + (kb + (qm & 1) * 8) * 2);
                uint32_t t0, t1, t2, t3;
                asm volatile("ldmatrix.sync.aligned.m8n8.x4.shared.b16 {%0,%1,%2,%3}, [%4];"
                             : "=r"(t0), "=r"(t1), "=r"(t2), "=r"(t3) : "r"(adr));
                bh[0][0] = t0; bh[0][1] = t1; bh[1][0] = t2; bh[1][1] = t3;
                asm volatile("ldmatrix.sync.aligned.m8n8.x4.shared.b16 {%0,%1,%2,%3}, [%4];"
                             : "=r"(t0), "=r"(t1), "=r"(t2), "=r"(t3) : "r"(adr + 5120));
                bl[0][0] = t0; bl[0][1] = t1; bl[1][0] = t2; bl[1][1] = t3;
            }
#pragma unroll
            for (int mi = 0; mi < 4; mi++)
#pragma unroll
                for (int ni = 0; ni < 2; ni++) {
                    mma16816(acc[mi][ni], ah[mi], bh[ni]);
                    mma16816(acc[mi][ni], ah[mi], bl[ni]);
                    mma16816(acc[mi][ni], al[mi], bh[ni]);
                }
        }
        __syncthreads();
        cur ^= 1;
    }
#undef RLOAD

#pragma unroll
    for (int mi = 0; mi < 4; mi++)
#pragma unroll
        for (int half = 0; half < 2; ++half) {
            int r = mi * 16 + g + half * 8;
#pragma unroll
            for (int ni = 0; ni < 2; ni++) {
                int col = n0 + wid * 16 + ni * 8 + 2 * tg;
                float2 v;
                v.x = acc[mi][ni][half * 2 + 0];
                v.y = acc[mi][ni][half * 2 + 1];
                if (MODE == 1) {
                    v.x += bias1[col];     v.y += bias1[col + 1];
                    if (bias2) { v.x += bias2[col]; v.y += bias2[col + 1]; }
                    *(float2*)(C + (size_t)(m0 + r) * N + col) = v;
                } else {
                    *(float2*)(C + (size_t)slice * 64 * N + (size_t)r * N + col) = v;
                }
            }
        }
}

// ================= fused one-time fp32 -> hi/lo conversions ===============
// rows 0..4095: W_hh->Bh | 4096..5119: Wa->Bh | 5120..9215: W_ih[:, :1024]->Wx
// 9216..13311: W_ih[:,1024:]->Wc | 13312..14335: Ua | 14336..18431: enc
__global__ void __launch_bounds__(256)
conv_all(const float* __restrict__ Whh, const float* __restrict__ Wa,
         const float* __restrict__ Wih, const float* __restrict__ Ua,
         const float* __restrict__ enc)
{
    const int TOT4 = 18432 * 256;
    for (int idx = blockIdx.x * 256 + threadIdx.x; idx < TOT4;
         idx += gridDim.x * 256) {
        int row = idx >> 8, c4 = idx & 255;
        const float* src; __nv_bfloat16 *hi, *lo; size_t d4;
        if (row < 4096)       { src = Whh + ((size_t)row << 10);              hi = g_BhHi; lo = g_BhLo; d4 = (size_t)row * 256 + c4; }
        else if (row < 5120)  { int r = row - 4096; src = Wa + ((size_t)r << 10);   hi = g_BhHi; lo = g_BhLo; d4 = (size_t)row * 256 + c4; }
        else if (row < 9216)  { int r = row - 5120; src = Wih + ((size_t)r << 11);  hi = g_WxHi; lo = g_WxLo; d4 = (size_t)r * 256 + c4; }
        else if (row < 13312) { int r = row - 9216; src = Wih + ((size_t)r << 11) + 1024; hi = g_WcHi; lo = g_WcLo; d4 = (size_t)r * 256 + c4; }
        else if (row < 14336) { int r = row - 13312; src = Ua + ((size_t)r << 10);  hi = g_UaHi; lo = g_UaLo; d4 = (size_t)r * 256 + c4; }
        else                  { int r = row - 14336; src = enc + ((size_t)r << 10); hi = g_encHi; lo = g_encLo; d4 = (size_t)r * 256 + c4; }
        float4 v = ((const float4*)src)[c4];
        __nv_bfloat16 h0 = __float2bfloat16(v.x), h1 = __float2bfloat16(v.y);
        __nv_bfloat16 h2 = __float2bfloat16(v.z), h3 = __float2bfloat16(v.w);
        __nv_bfloat162* H = (__nv_bfloat162*)hi;
        H[d4 * 2]     = __halves2bfloat162(h0, h1);
        H[d4 * 2 + 1] = __halves2bfloat162(h2, h3);
        __nv_bfloat162* L = (__nv_bfloat162*)lo;
        L[d4 * 2]     = __floats2bfloat162_rn(v.x - __bfloat162float(h0), v.y - __bfloat162float(h1));
        L[d4 * 2 + 1] = __floats2bfloat162_rn(v.z - __bfloat162float(h2), v.w - __bfloat162float(h3));
    }
}

// ================= embedding gather for all steps (float4) ================
__global__ void __launch_bounds__(256)
gather_x(const float* __restrict__ emb, const int* __restrict__ target)
{
    int idx = blockIdx.x * 256 + threadIdx.x;   // float4 id, 896*256 total
    if (idx >= 896 * 256) return;
    int r = idx >> 8, c4 = idx & 255;
    float4 v = make_float4(0.f, 0.f, 0.f, 0.f);
    if (r < Tt * Bb) {
        int t = r >> 6, b = r & 63;
        int tok = (t == 0) ? SOS_TOK : target[b * Tt + (t - 1)];
        v = ((const float4*)(emb + ((size_t)tok << 10)))[c4];
    }
    __nv_bfloat16 h0 = __float2bfloat16(v.x), h1 = __float2bfloat16(v.y);
    __nv_bfloat16 h2 = __float2bfloat16(v.z), h3 = __float2bfloat16(v.w);
    __nv_bfloat162* H = (__nv_bfloat162*)g_xgHi;
    H[(size_t)idx * 2]     = __halves2bfloat162(h0, h1);
    H[(size_t)idx * 2 + 1] = __halves2bfloat162(h2, h3);
    __nv_bfloat162* L = (__nv_bfloat162*)g_xgLo;
    L[(size_t)idx * 2]     = __floats2bfloat162_rn(v.x - __bfloat162float(h0), v.y - __bfloat162float(h1));
    L[(size_t)idx * 2 + 1] = __floats2bfloat162_rn(v.z - __bfloat162float(h2), v.w - __bfloat162float(h3));
}

// ======== scores: block (b, s-group of 8); dual-pipe tanh ================
__global__ void __launch_bounds__(256)
scores_k(const float* __restrict__ Va, const float* __restrict__ ba,
         const float* __restrict__ bv)
{
    const int b = blockIdx.x;
    const int tid = threadIdx.x;
    const int wid = tid >> 5, lane = tid & 31;
    __shared__ float qs[Hd], vas[Hd];

    for (int k = tid; k < Hd; k += 256) {
        qs[k] = g_hp[0][b * NB5 + 4096 + k] + g_hp[1][b * NB5 + 4096 + k]
              + g_hp[2][b * NB5 + 4096 + k] + g_hp[3][b * NB5 + 4096 + k] + ba[k];
        vas[k] = Va[k];
    }
    __syncthreads();

    const int s = blockIdx.y * 8 + wid;
    const float* kr = g_keys + ((size_t)(b * Ss + s)) * Hd;
    float acc = 0.f;
#pragma unroll
    for (int i = 0; i < 32; i++) {
        int k = i * 32 + lane;
        float v = qs[k] + kr[k];
        float th = ((i & 15) < 7) ? tanh_mufu(v) : tanh_poly(v);
        acc += th * vas[k];
    }
#pragma unroll
    for (int o = 16; o; o >>= 1) acc += __shfl_xor_sync(0xffffffffu, acc, o);
    if (lane == 0) g_sc[b * Ss + s] = acc + bv[0];
}

// ====== ctx: softmax + context -> hi/lo planes + attn write ===============
__global__ void __launch_bounds__(128)
ctx_k(const float* __restrict__ enc, float* __restrict__ out_attn, int t)
{
    const int b = blockIdx.x, hc = blockIdx.y;
    const int tid = threadIdx.x;
    __shared__ float w[Ss];

    if (tid < Ss) w[tid] = g_sc[b * Ss + tid];
    __syncthreads();
    if (tid < 32) {
        float v0 = w[tid], v1 = w[tid + 32];
        float m = fmaxf(v0, v1);
#pragma unroll
        for (int o = 16; o; o >>= 1) m = fmaxf(m, __shfl_xor_sync(0xffffffffu, m, o));
        float e0 = __expf(v0 - m), e1 = __expf(v1 - m);
        float sum = e0 + e1;
#pragma unroll
        for (int o = 16; o; o >>= 1) sum += __shfl_xor_sync(0xffffffffu, sum, o);
        float inv = 1.f / sum;
        w[tid] = e0 * inv; w[tid + 32] = e1 * inv;
    }
    __syncthreads();

    if (hc == 0 && tid < Ss) out_attn[((size_t)b * Tt + t) * Ss + tid] = w[tid];

    const int h = hc * 128 + tid;
    float acc = 0.f;
#pragma unroll 8
    for (int s = 0; s < Ss; s++)
        acc += w[s] * enc[((size_t)(b * Ss + s)) * Hd + h];
    __nv_bfloat16 chi = __float2bfloat16(acc);
    g_ctxHi[b * Hd + h] = chi;
    g_ctxLo[b * Hd + h] = __float2bfloat16(acc - __bfloat162float(chi));
}

// ====== cell: gates = xpre + 4 hp + 4 cp ; LSTM ; LayerNorm -> bf16 nh ====
__global__ void __launch_bounds__(256)
cell_k(const float* __restrict__ ln_g, const float* __restrict__ ln_b, int t)
{
    const int b = blockIdx.x, tid = threadIdx.x;
    const int wid = tid >> 5, lane = tid & 31;
    __shared__ float r1[8], r2[8];
    const size_t xr = (size_t)(t * Bb + b) * 4096;

    float hv[4];
    float s1 = 0.f, s2 = 0.f;
#pragma unroll
    for (int i = 0; i < 4; i++) {
        int j = tid + i * 256;
        float vi = g_xpre[xr + j];
        float vf = g_xpre[xr + Hd + j];
        float vg = g_xpre[xr + 2 * Hd + j];
        float vo = g_xpre[xr + 3 * Hd + j];
#pragma unroll
        for (int s = 0; s < 4; s++) {
            const float* hp = g_hp[s] + (size_t)b * NB5;
            vi += hp[j]; vf += hp[Hd + j]; vg += hp[2 * Hd + j]; vo += hp[3 * Hd + j];
        }
#pragma unroll
        for (int s = 0; s < 4; s++) {
            const float* cp = g_cp[s] + (size_t)b * 4096;
            vi += cp[j]; vf += cp[Hd + j]; vg += cp[2 * Hd + j]; vo += cp[3 * Hd + j];
        }
        float cv = sigmoid_fast(vf) * g_c[b * Hd + j] + sigmoid_fast(vi) * tanh_mufu(vg);
        g_c[b * Hd + j] = cv;
        float hh = sigmoid_fast(vo) * tanh_mufu(cv);
        g_h[b * Hd + j] = hh;
        __nv_bfloat16 hb = __float2bfloat16(hh);
        g_hHi[b * Hd + j] = hb;
        g_hLo[b * Hd + j] = __float2bfloat16(hh - __bfloat162float(hb));
        hv[i] = hh; s1 += hh; s2 += hh * hh;
    }
#pragma unroll
    for (int o = 16; o; o >>= 1) {
        s1 += __shfl_xor_sync(0xffffffffu, s1, o);
        s2 += __shfl_xor_sync(0xffffffffu, s2, o);
    }
    if (lane == 0) { r1[wid] = s1; r2[wid] = s2; }
    __syncthreads();
    if (wid == 0) {
        float a = (lane < 8) ? r1[lane] : 0.f;
        float q = (lane < 8) ? r2[lane] : 0.f;
#pragma unroll
        for (int o = 4; o; o >>= 1) {
            a += __shfl_xor_sync(0xffffffffu, a, o);
            q += __shfl_xor_sync(0xffffffffu, q, o);
        }
        if (lane == 0) { r1[0] = a; r2[0] = q; }
    }
    __syncthreads();
    float mu  = r1[0] * (1.f / Hd);
    float var = r2[0] * (1.f / Hd) - mu * mu;
    float inv = rsqrtf(var + 1e-5f);
#pragma unroll
    for (int i = 0; i < 4; i++) {
        int j = tid + i * 256;
        float nhv = (hv[i] - mu) * inv * ln_g[j] + ln_b[j];
        g_nhb[((size_t)t * Bb + b) * Hd + j] = __float2bfloat16(nhv);
    }
}

// ================= big logits GEMM ========================================
__global__ void __launch_bounds__(256)
logits_gemm(const __nv_bfloat16* __restrict__ A, const __nv_bfloat16* __restrict__ Bw,
            const float* __restrict__ bias, float* __restrict__ out)
{
    __shared__ __nv_bfloat16 As[2][128][40];
    __shared__ __nv_bfloat16 Bs[2][128][40];

    const int tid = threadIdx.x;
    const int wid = tid >> 5, lane = tid & 31;
    const int wm = wid & 1, wn = wid >> 1;
    const int g  = lane >> 2, tg = lane & 3;
    const int m0 = blockIdx.y * 128, n0 = blockIdx.x * 128;

    const uint32_t sA = (uint32_t)__cvta_generic_to_shared(&As[0][0][0]);
    const uint32_t sB = (uint32_t)__cvta_generic_to_shared(&Bs[0][0][0]);

    float acc[4][4][4];
#pragma unroll
    for (int a = 0; a < 4; a++)
#pragma unroll
        for (int b = 0; b < 4; b++)
#pragma unroll
            for (int c = 0; c < 4; c++) acc[a][b][c] = 0.f;

    const int idx0 = tid, idx1 = tid + 256;
    const int r0 = idx0 >> 2, c0 = (idx0 & 3) * 8;
    const int r1 = idx1 >> 2, c1 = (idx1 & 3) * 8;

#define LOAD_STAGE(st, k0)                                                          \
    {                                                                               \
        uint32_t da0 = sA + (uint32_t)((st) * 10240 + r0 * 80 + c0 * 2);            \
        uint32_t da1 = sA + (uint32_t)((st) * 10240 + r1 * 80 + c1 * 2);            \
        uint32_t db0 = sB + (uint32_t)((st) * 10240 + r0 * 80 + c0 * 2);            \
        uint32_t db1 = sB + (uint32_t)((st) * 10240 + r1 * 80 + c1 * 2);            \
        const __nv_bfloat16* sa0 = A + (size_t)(m0 + r0) * Hd + (k0) + c0;          \
        const __nv_bfloat16* sa1 = A + (size_t)(m0 + r1) * Hd + (k0) + c1;          \
        const __nv_bfloat16* sb0 = Bw + (size_t)(n0 + r0) * Hd + (k0) + c0;         \
        const __nv_bfloat16* sb1 = Bw + (size_t)(n0 + r1) * Hd + (k0) + c1;         \
        asm volatile("cp.async.cg.shared.global [%0], [%1], 16;\n" ::"r"(da0), "l"(sa0)); \
        asm volatile("cp.async.cg.shared.global [%0], [%1], 16;\n" ::"r"(da1), "l"(sa1)); \
        asm volatile("cp.async.cg.shared.global [%0], [%1], 16;\n" ::"r"(db0), "l"(sb0)); \
        asm volatile("cp.async.cg.shared.global [%0], [%1], 16;\n" ::"r"(db1), "l"(sb1)); \
    }

    LOAD_STAGE(0, 0)
    asm volatile("cp.async.commit_group;\n" ::: "memory");

    const int qm = lane >> 3, lr = lane & 7;

    int cur = 0;
#pragma unroll 1
    for (int k0 = 0; k0 < Hd; k0 += 32) {
        asm volatile("cp.async.wait_group 0;\n" ::: "memory");
        __syncthreads();
        if (k0 + 32 < Hd) {
            LOAD_STAGE(cur ^ 1, k0 + 32)
            asm volatile("cp.async.commit_group;\n" ::: "memory");
        }

#pragma unroll
        for (int ki = 0; ki < 2; ++ki) {
            const int kb = ki * 16;
            uint32_t af[4][4], bf[4][2];
#pragma unroll
            for (int mi = 0; mi < 4; mi++) {
                int rr = wm * 64 + mi * 16;
                uint32_t addr = sA + (uint32_t)(cur * 10240
                              + (rr + lr + (qm & 1) * 8) * 80
                              + (kb + (qm >> 1) * 8) * 2);
                asm volatile("ldmatrix.sync.aligned.m8n8.x4.shared.b16 {%0,%1,%2,%3}, [%4];"
                             : "=r"(af[mi][0]), "=r"(af[mi][1]), "=r"(af[mi][2]), "=r"(af[mi][3])
                             : "r"(addr));
            }
#pragma unroll
            for (int np = 0; np < 2; np++) {
                int nr = wn * 32 + np * 16;
                uint32_t addr = sB + (uint32_t)(cur * 10240
                              + (nr + lr + (qm >> 1) * 8) * 80
                              + (kb + (qm & 1) * 8) * 2);
                uint32_t t0, t1, t2, t3;
                asm volatile("ldmatrix.sync.aligned.m8n8.x4.shared.b16 {%0,%1,%2,%3}, [%4];"
                             : "=r"(t0), "=r"(t1), "=r"(t2), "=r"(t3)
                             : "r"(addr));
                bf[np * 2][0] = t0; bf[np * 2][1] = t1;
                bf[np * 2 + 1][0] = t2; bf[np * 2 + 1][1] = t3;
            }
#pragma unroll
            for (int mi = 0; mi < 4; mi++)
#pragma unroll
                for (int ni = 0; ni < 4; ni++)
                    mma16816(acc[mi][ni], af[mi], bf[ni]);
        }
        __syncthreads();
        cur ^= 1;
    }

#pragma unroll
    for (int mi = 0; mi < 4; mi++)
#pragma unroll
        for (int half = 0; half < 2; ++half) {
            int row = m0 + wm * 64 + mi * 16 + g + half * 8;
            if (row < Tt * Bb) {
                size_t orow = (size_t)(row & 63) * Tt + (row >> 6);
#pragma unroll
                for (int ni = 0; ni < 4; ni++) {
                    int col = n0 + wn * 32 + ni * 8 + 2 * tg;
                    float2 v;
                    v.x = acc[mi][ni][half * 2 + 0] + bias[col];
                    v.y = acc[mi][ni][half * 2 + 1] + bias[col + 1];
                    *(float2*)(out + orow * (size_t)Vv + col) = v;
                }
            }
        }
#undef LOAD_STAGE
}

// ---------------- outW fp32 -> bf16 --------------------------------------
__global__ void __launch_bounds__(256)
convW(const float* __restrict__ W)
{
    size_t i = (size_t)blockIdx.x * 256 + threadIdx.x;
    if (i < ((size_t)Vv * Hd) / 4) {
        float4 v = ((const float4*)W)[i];
        __nv_bfloat162* d = (__nv_bfloat162*)g_outWb;
        d[i * 2]     = __floats2bfloat162_rn(v.x, v.y);
        d[i * 2 + 1] = __floats2bfloat162_rn(v.z, v.w);
    }
}

// ---------------- single-pass online log-softmax --------------------------
__global__ void __launch_bounds__(512)
logsoftmax(float* __restrict__ out)
{
    const size_t base = (size_t)blockIdx.x * Vv;
    const int tid = threadIdx.x;
    const int wid = tid >> 5, lane = tid & 31;
    __shared__ float rm[16], rs[16], fin[2];

    float m = -1e30f, s = 0.f;
    const float4* p = (const float4*)(out + base);
    for (int i = tid; i < Vv / 4; i += 512) {
        float4 v = p[i];
        float xs[4] = {v.x, v.y, v.z, v.w};
#pragma unroll
        for (int e = 0; e < 4; e++) {
            float nm = fmaxf(m, xs[e]);
            s = s * __expf(m - nm) + __expf(xs[e] - nm);
            m = nm;
        }
    }
#pragma unroll
    for (int o = 16; o; o >>= 1) {
        float om = __shfl_xor_sync(0xffffffffu, m, o);
        float os = __shfl_xor_sync(0xffffffffu, s, o);
        float nm = fmaxf(m, om);
        s = s * __expf(m - nm) + os * __expf(om - nm);
        m = nm;
    }
    if (lane == 0) { rm[wid] = m; rs[wid] = s; }
    __syncthreads();
    if (wid == 0) {
        float mm = (lane < 16) ? rm[lane] : -1e30f;
        float ss = (lane < 16) ? rs[lane] : 0.f;
#pragma unroll
        for (int o = 8; o; o >>= 1) {
            float om = __shfl_xor_sync(0xffffffffu, mm, o);
            float os = __shfl_xor_sync(0xffffffffu, ss, o);
            float nm = fmaxf(mm, om);
            ss = ss * __expf(mm - nm) + os * __expf(om - nm);
            mm = nm;
        }
        if (lane == 0) { fin[0] = mm; fin[1] = ss; }
    }
    __syncthreads();
    float lse = fin[0] + logf(fin[1]);
    float4* q = (float4*)(out + base);
    for (int i = tid; i < Vv / 4; i += 512) {
        float4 v = q[i];
        v.x -= lse; v.y -= lse; v.z -= lse; v.w -= lse;
        q[i] = v;
    }
}

// ---------------- state init / final copies ------------------------------
__global__ void init_state(const float* __restrict__ h0, const float* __restrict__ c0)
{
    int i = blockIdx.x * blockDim.x + threadIdx.x;
    if (i < Bb * Hd) {
        float hv = h0[i];
        g_h[i] = hv; g_c[i] = c0[i];
        __nv_bfloat16 hb = __float2bfloat16(hv);
        g_hHi[i] = hb;
        g_hLo[i] = __float2bfloat16(hv - __bfloat162float(hb));
        g_nhb[(size_t)(Tt * Bb) * Hd + i] = __float2bfloat16(0.f);  // pad rows
    }
}

__global__ void copy_hc(float* __restrict__ out)
{
    int i = blockIdx.x * blockDim.x + threadIdx.x;
    if (i < Bb * Hd) {
        out[(size_t)Bb * Tt * Vv + i] = g_h[i];
        out[(size_t)Bb * Tt * Vv + (size_t)Bb * Hd + i] = g_c[i];
    }
}

// ---------------- launch ---------------------------------------------------
extern "C" void kernel_launch(void* const* d_in, const int* in_sizes, int n_in,
                              void* d_out, int out_size)
{
    (void)in_sizes; (void)n_in; (void)out_size;
    const float* enc    = (const float*)d_in[0];
    const float* enc_h  = (const float*)d_in[1];
    const float* enc_c  = (const float*)d_in[2];
    const int*   target = (const int*)  d_in[3];
    const float* emb    = (const float*)d_in[4];
    const float* Wa     = (const float*)d_in[5];
    const float* ba     = (const float*)d_in[6];
    const float* Ua     = (const float*)d_in[7];
    const float* bu     = (const float*)d_in[8];
    const float* Va     = (const float*)d_in[9];
    const float* bv     = (const float*)d_in[10];
    const float* W_ih   = (const float*)d_in[11];
    const float* W_hh   = (const float*)d_in[12];
    const float* b_ih   = (const float*)d_in[13];
    const float* b_hh   = (const float*)d_in[14];
    const float* ln_g   = (const float*)d_in[15];
    const float* ln_b   = (const float*)d_in[16];
    const float* outW   = (const float*)d_in[17];
    const float* outb   = (const float*)d_in[18];
    float* out = (float*)d_out;

    float *keys, *hp, *cp, *xpre;
    __nv_bfloat16 *hHi, *hLo, *ctxHi, *ctxLo, *encHi, *encLo, *UaHi, *UaLo;
    __nv_bfloat16 *BhHi, *BhLo, *WxHi, *WxLo, *WcHi, *WcLo, *xgHi, *xgLo;
    __nv_bfloat16 *nhb, *outWb;
    cudaGetSymbolAddress((void**)&keys,  g_keys);
    cudaGetSymbolAddress((void**)&hp,    g_hp);
    cudaGetSymbolAddress((void**)&cp,    g_cp);
    cudaGetSymbolAddress((void**)&xpre,  g_xpre);
    cudaGetSymbolAddress((void**)&hHi,   g_hHi);
    cudaGetSymbolAddress((void**)&hLo,   g_hLo);
    cudaGetSymbolAddress((void**)&ctxHi, g_ctxHi);
    cudaGetSymbolAddress((void**)&ctxLo, g_ctxLo);
    cudaGetSymbolAddress((void**)&encHi, g_encHi);
    cudaGetSymbolAddress((void**)&encLo, g_encLo);
    cudaGetSymbolAddress((void**)&UaHi,  g_UaHi);
    cudaGetSymbolAddress((void**)&UaLo,  g_UaLo);
    cudaGetSymbolAddress((void**)&BhHi,  g_BhHi);
    cudaGetSymbolAddress((void**)&BhLo,  g_BhLo);
    cudaGetSymbolAddress((void**)&WxHi,  g_WxHi);
    cudaGetSymbolAddress((void**)&WxLo,  g_WxLo);
    cudaGetSymbolAddress((void**)&WcHi,  g_WcHi);
    cudaGetSymbolAddress((void**)&WcLo,  g_WcLo);
    cudaGetSymbolAddress((void**)&xgHi,  g_xgHi);
    cudaGetSymbolAddress((void**)&xgLo,  g_xgLo);
    cudaGetSymbolAddress((void**)&nhb,   g_nhb);
    cudaGetSymbolAddress((void**)&outWb, g_outWb);

    float* out_attn = out + (size_t)Bb * Tt * Vv + 2 * (size_t)Bb * Hd;

    init_state<<<(Bb * Hd + 511) / 512, 512>>>(enc_h, enc_c);
    convW<<<(int)(((size_t)Vv * Hd / 4 + 255) / 256), 256>>>(outW);
    conv_all<<<2048, 256>>>(W_hh, Wa, W_ih, Ua, enc);
    gather_x<<<896, 256>>>(emb, target);

    // xpre = xg @ W_ihx^T + b_ih + b_hh   [896 x 4096]
    rgemm<1><<<dim3(64, 1, 14), 128>>>(xgHi, xgLo, WxHi, WxLo,
                                       Hd, Hd, 4096, xpre, b_ih, b_hh);
    // keys = enc @ Ua^T + bu   [4096 x 1024]
    rgemm<1><<<dim3(16, 1, 64), 128>>>(encHi, encLo, UaHi, UaLo,
                                       Hd, Hd, Hd, keys, bu, nullptr);

    for (int t = 0; t < Tt; t++) {
        // h @ [W_hh | Wa]^T partials  (N=5120, 4 k-slices)
        rgemm<0><<<dim3(80, 4, 1), 128>>>(hHi, hLo, BhHi, BhLo,
                                          Hd, 256, NB5, hp, nullptr, nullptr);
        scores_k<<<dim3(Bb, 8), 256>>>(Va, ba, bv);
        ctx_k<<<dim3(Bb, 8), 128>>>(enc, out_attn, t);
        // ctx @ W_ihc^T partials  (N=4096, 4 k-slices)
        rgemm<0><<<dim3(64, 4, 1), 128>>>(ctxHi, ctxLo, WcHi, WcLo,
                                          Hd, 256, 4096, cp, nullptr, nullptr);
        cell_k<<<Bb, 256>>>(ln_g, ln_b, t);
    }

    logits_gemm<<<dim3(Vv / 128, 7), 256>>>(nhb, outWb, outb, out);
    logsoftmax<<<Tt * Bb, 512>>>(out);
    copy_hc<<<(Bb * Hd + 511) / 512, 512>>>(out);
}